// round 9
// baseline (speedup 1.0000x reference)
#include <cuda_runtime.h>
#include <cuda_bf16.h>
#include <cstdint>

// ---------------------------------------------------------------------------
// TinyFormerEncoder R8: batch-paired tensor-core kernel.
// Same split-precision (hi+lo, 3-term) m16n8k16 bf16 mma as R7, but each warp
// processes TWO batches per gemm pass: every weight B-fragment load feeds
// 6 mma (3 terms x 2 batches), halving the dominant LDS traffic (L1 was 85%).
// Attention gemms (S = QK^T, ctx = PV) remain per-batch (private K/V staging,
// now 2 staging slots per warp).
// ---------------------------------------------------------------------------

namespace {
constexpr int THREADS = 128;          // 4 warps
constexpr int NB = 8;                 // batches per warp (4 pairs)
constexpr int BATCHES_PER_BLOCK = 4 * NB;  // 32

// ushort (bf16) offsets in dynamic smem
constexpr int WQH = 0,     WQL = 1152;
constexpr int WKH = 2304,  WKL = 3456;
constexpr int WVH = 4608,  WVL = 5760;
constexpr int WOH = 6912,  WOL = 8064;     // 32x32 mats, row stride 36
constexpr int W1H = 9216,  W1L = 11520;    // 64 rows x stride 36
constexpr int W2H = 13824, W2L = 16128;    // 32 rows x stride 72
constexpr int BIASU  = 18432;              // float bias block starts here
constexpr int STAGEU = 18880;              // per-warp staging base (ushort)
constexpr int BATCH_STAGE = 2688;          // ushorts per batch slot
constexpr int WARP_STAGE  = 2 * BATCH_STAGE;
constexpr int KH = 0, KL = 576;            // K planes: 16 rows x stride 36
constexpr int VTH = 1152, VTL = 1920;      // vT planes: 32 rows x stride 24
constexpr int SMEM_BYTES = (STAGEU + 4 * WARP_STAGE) * 2;  // 80768
constexpr float SCALE = 0.17677669529663687f;  // 1/sqrt(32)
}

__device__ __forceinline__ uint32_t packbf(float lo, float hi) {
    uint32_t r;
    asm("cvt.rn.bf16x2.f32 %0, %1, %2;" : "=r"(r) : "f"(hi), "f"(lo));
    return r;
}
__device__ __forceinline__ float lo2f(uint32_t v) { return __uint_as_float(v << 16); }
__device__ __forceinline__ float hi2f(uint32_t v) { return __uint_as_float(v & 0xffff0000u); }

__device__ __forceinline__ void split2(float e0, float e1, uint32_t &h, uint32_t &l) {
    h = packbf(e0, e1);
    l = packbf(e0 - lo2f(h), e1 - hi2f(h));
}

__device__ __forceinline__ void mma16816(float &c0, float &c1, float &c2, float &c3,
                                         uint32_t a0, uint32_t a1, uint32_t a2, uint32_t a3,
                                         uint32_t b0, uint32_t b1) {
    asm("mma.sync.aligned.m16n8k16.row.col.f32.bf16.bf16.f32 "
        "{%0,%1,%2,%3}, {%4,%5,%6,%7}, {%8,%9}, {%0,%1,%2,%3};"
        : "+f"(c0), "+f"(c1), "+f"(c2), "+f"(c3)
        : "r"(a0), "r"(a1), "r"(a2), "r"(a3), "r"(b0), "r"(b1));
}

// 3-term split mma for one batch on a loaded B quad
__device__ __forceinline__ void mma3(float *c, const uint32_t *ah, const uint32_t *al,
                                     uint32_t bh0, uint32_t bh1, uint32_t bl0, uint32_t bl1) {
    mma16816(c[0],c[1],c[2],c[3], ah[0],ah[1],ah[2],ah[3], bh0,bh1);
    mma16816(c[0],c[1],c[2],c[3], ah[0],ah[1],ah[2],ah[3], bl0,bl1);
    mma16816(c[0],c[1],c[2],c[3], al[0],al[1],al[2],al[3], bh0,bh1);
}

// C-fragment -> A-fragments, split hi/lo
template <int KCH>
__device__ __forceinline__ void c2a(const float *C, uint32_t *ah, uint32_t *al) {
#pragma unroll
    for (int kc = 0; kc < KCH; kc++) {
        split2(C[8*kc+0], C[8*kc+1], ah[kc*4+0], al[kc*4+0]);
        split2(C[8*kc+2], C[8*kc+3], ah[kc*4+1], al[kc*4+1]);
        split2(C[8*kc+4], C[8*kc+5], ah[kc*4+2], al[kc*4+2]);
        split2(C[8*kc+6], C[8*kc+7], ah[kc*4+3], al[kc*4+3]);
    }
}

// Single-batch split GEMM (for per-batch attention ops)
template <int KCH, int NCH, int RS>
__device__ __forceinline__ void gemm(float *C, const uint32_t *ah, const uint32_t *al,
                                     const unsigned short *wh, const unsigned short *wl,
                                     int g, int t) {
#pragma unroll
    for (int j = 0; j < NCH; j++) {
#pragma unroll
        for (int kc = 0; kc < KCH; kc++) {
            const unsigned short *ph = wh + (8*j + g)*RS + kc*16 + 2*t;
            const unsigned short *pl = wl + (8*j + g)*RS + kc*16 + 2*t;
            uint32_t bh0 = *(const uint32_t*)ph, bh1 = *(const uint32_t*)(ph + 8);
            uint32_t bl0 = *(const uint32_t*)pl, bl1 = *(const uint32_t*)(pl + 8);
            mma3(C + j*4, ah + kc*4, al + kc*4, bh0, bh1, bl0, bl1);
        }
    }
}

// Batch-paired split GEMM: one B quad feeds both batches (6 mma per quad)
template <int KCH, int NCH, int RS>
__device__ __forceinline__ void gemm2(float *CA, float *CB,
                                      const uint32_t *ahA, const uint32_t *alA,
                                      const uint32_t *ahB, const uint32_t *alB,
                                      const unsigned short *wh, const unsigned short *wl,
                                      int g, int t) {
#pragma unroll
    for (int j = 0; j < NCH; j++) {
#pragma unroll
        for (int kc = 0; kc < KCH; kc++) {
            const unsigned short *ph = wh + (8*j + g)*RS + kc*16 + 2*t;
            const unsigned short *pl = wl + (8*j + g)*RS + kc*16 + 2*t;
            uint32_t bh0 = *(const uint32_t*)ph, bh1 = *(const uint32_t*)(ph + 8);
            uint32_t bl0 = *(const uint32_t*)pl, bl1 = *(const uint32_t*)(pl + 8);
            mma3(CA + j*4, ahA + kc*4, alA + kc*4, bh0, bh1, bl0, bl1);
            mma3(CB + j*4, ahB + kc*4, alB + kc*4, bh0, bh1, bl0, bl1);
        }
    }
}

__global__ void __launch_bounds__(THREADS, 2)
tinyformer_tc_kernel(const float *__restrict__ x,
                     const float *__restrict__ Wq, const float *__restrict__ bq,
                     const float *__restrict__ Wk, const float *__restrict__ bk,
                     const float *__restrict__ Wv, const float *__restrict__ bv,
                     const float *__restrict__ Wo, const float *__restrict__ bo,
                     const float *__restrict__ W1, const float *__restrict__ b1,
                     const float *__restrict__ W2, const float *__restrict__ b2,
                     float *__restrict__ out, int B)
{
    extern __shared__ unsigned short sm16[];
    float *smf = (float*)(sm16 + BIASU);
    const int tid = threadIdx.x;

    // ---- stage weights: transpose + split into bf16 hi/lo planes ----
    for (int i = tid; i < 1024; i += THREADS) {
        int d = i >> 5, j = i & 31;
        int o = j*36 + d;
        {   float v = Wq[i]; uint32_t p = packbf(v, 0.f);
            sm16[WQH + o] = (unsigned short)p;
            sm16[WQL + o] = (unsigned short)packbf(v - lo2f(p), 0.f); }
        {   float v = Wk[i]; uint32_t p = packbf(v, 0.f);
            sm16[WKH + o] = (unsigned short)p;
            sm16[WKL + o] = (unsigned short)packbf(v - lo2f(p), 0.f); }
        {   float v = Wv[i]; uint32_t p = packbf(v, 0.f);
            sm16[WVH + o] = (unsigned short)p;
            sm16[WVL + o] = (unsigned short)packbf(v - lo2f(p), 0.f); }
        {   float v = Wo[i]; uint32_t p = packbf(v, 0.f);
            sm16[WOH + o] = (unsigned short)p;
            sm16[WOL + o] = (unsigned short)packbf(v - lo2f(p), 0.f); }
    }
    for (int i = tid; i < 2048; i += THREADS) {
        {   int d = i >> 6, j = i & 63;
            float v = W1[i]; uint32_t p = packbf(v, 0.f);
            sm16[W1H + j*36 + d] = (unsigned short)p;
            sm16[W1L + j*36 + d] = (unsigned short)packbf(v - lo2f(p), 0.f); }
        {   int h = i >> 5, j = i & 31;
            float v = W2[i]; uint32_t p = packbf(v, 0.f);
            sm16[W2H + j*72 + h] = (unsigned short)p;
            sm16[W2L + j*72 + h] = (unsigned short)packbf(v - lo2f(p), 0.f); }
    }
    if (tid < 32) {
        smf[0   + tid] = bq[tid]; smf[32 + tid] = bk[tid]; smf[64 + tid] = bv[tid];
        smf[96  + tid] = bo[tid]; smf[192 + tid] = b2[tid];
    }
    if (tid < 64) smf[128 + tid] = b1[tid];
    __syncthreads();

    const int warp = tid >> 5, lane = tid & 31;
    const int g = lane >> 2, t = lane & 3;
    unsigned short *stgA = sm16 + STAGEU + warp * WARP_STAGE;
    unsigned short *stgB = stgA + BATCH_STAGE;

    for (int it = 0; it < NB/2; it++) {
        size_t b0 = (size_t)blockIdx.x * BATCHES_PER_BLOCK + warp * NB + 2*it;
        if (b0 >= (size_t)B) continue;           // warp-uniform
        size_t b1s = b0 + 1;
        const bool v1 = b1s < (size_t)B;
        if (!v1) b1s = b0;

        // ---- x (both batches) in C-fragment layout, fp32 ----
        const float2 *xpA = (const float2*)(x + b0 * 512);
        const float2 *xpB = (const float2*)(x + b1s * 512);
        float xcA[16], xcB[16];
#pragma unroll
        for (int nc = 0; nc < 4; nc++) {
            float2 p0 = xpA[g*16 + nc*4 + t], p1 = xpA[(g+8)*16 + nc*4 + t];
            xcA[nc*4+0] = p0.x; xcA[nc*4+1] = p0.y;
            xcA[nc*4+2] = p1.x; xcA[nc*4+3] = p1.y;
            float2 q0 = xpB[g*16 + nc*4 + t], q1 = xpB[(g+8)*16 + nc*4 + t];
            xcB[nc*4+0] = q0.x; xcB[nc*4+1] = q0.y;
            xcB[nc*4+2] = q1.x; xcB[nc*4+3] = q1.y;
        }
        uint32_t xahA[8], xalA[8], xahB[8], xalB[8];
        c2a<2>(xcA, xahA, xalA);
        c2a<2>(xcB, xahB, xalB);

        float CA[16], CB[16];

        // ---- K (both) -> split-stored row-major per staging slot ----
#pragma unroll
        for (int i2 = 0; i2 < 16; i2++) { CA[i2] = 0.f; CB[i2] = 0.f; }
        gemm2<2,4,36>(CA, CB, xahA, xalA, xahB, xalB, sm16 + WKH, sm16 + WKL, g, t);
#pragma unroll
        for (int nc = 0; nc < 4; nc++) {
            float2 bb = *(const float2*)(smf + 32 + 8*nc + 2*t);
            int c0 = nc*8 + 2*t;
            uint32_t h0, l0, h1, l1;
            split2(CA[nc*4+0] + bb.x, CA[nc*4+1] + bb.y, h0, l0);
            split2(CA[nc*4+2] + bb.x, CA[nc*4+3] + bb.y, h1, l1);
            *(uint32_t*)(stgA + KH + g*36     + c0) = h0;
            *(uint32_t*)(stgA + KL + g*36     + c0) = l0;
            *(uint32_t*)(stgA + KH + (g+8)*36 + c0) = h1;
            *(uint32_t*)(stgA + KL + (g+8)*36 + c0) = l1;
            split2(CB[nc*4+0] + bb.x, CB[nc*4+1] + bb.y, h0, l0);
            split2(CB[nc*4+2] + bb.x, CB[nc*4+3] + bb.y, h1, l1);
            *(uint32_t*)(stgB + KH + g*36     + c0) = h0;
            *(uint32_t*)(stgB + KL + g*36     + c0) = l0;
            *(uint32_t*)(stgB + KH + (g+8)*36 + c0) = h1;
            *(uint32_t*)(stgB + KL + (g+8)*36 + c0) = l1;
        }

        // ---- V (both) -> split-stored TRANSPOSED ----
#pragma unroll
        for (int i2 = 0; i2 < 16; i2++) { CA[i2] = 0.f; CB[i2] = 0.f; }
        gemm2<2,4,36>(CA, CB, xahA, xalA, xahB, xalB, sm16 + WVH, sm16 + WVL, g, t);
#pragma unroll
        for (int nc = 0; nc < 4; nc++) {
            float2 bb = *(const float2*)(smf + 64 + 8*nc + 2*t);
            int col0 = 8*nc + 2*t;
#pragma unroll
            for (int m = 0; m < 4; m++) {
                int col = col0 + (m & 1);
                int row = (m < 2) ? g : g + 8;
                float eA = CA[nc*4+m] + ((m & 1) ? bb.y : bb.x);
                uint32_t pA = packbf(eA, 0.f);
                stgA[VTH + col*24 + row] = (unsigned short)pA;
                stgA[VTL + col*24 + row] = (unsigned short)packbf(eA - lo2f(pA), 0.f);
                float eB = CB[nc*4+m] + ((m & 1) ? bb.y : bb.x);
                uint32_t pB = packbf(eB, 0.f);
                stgB[VTH + col*24 + row] = (unsigned short)pB;
                stgB[VTL + col*24 + row] = (unsigned short)packbf(eB - lo2f(pB), 0.f);
            }
        }

        // ---- Q (both) -> scaled A-fragments ----
#pragma unroll
        for (int i2 = 0; i2 < 16; i2++) { CA[i2] = 0.f; CB[i2] = 0.f; }
        gemm2<2,4,36>(CA, CB, xahA, xalA, xahB, xalB, sm16 + WQH, sm16 + WQL, g, t);
        uint32_t qahA[8], qalA[8], qahB[8], qalB[8];
        {
            float qc[16];
#pragma unroll
            for (int nc = 0; nc < 4; nc++) {
                float2 bb = *(const float2*)(smf + 0 + 8*nc + 2*t);
                qc[nc*4+0] = (CA[nc*4+0] + bb.x) * SCALE;
                qc[nc*4+1] = (CA[nc*4+1] + bb.y) * SCALE;
                qc[nc*4+2] = (CA[nc*4+2] + bb.x) * SCALE;
                qc[nc*4+3] = (CA[nc*4+3] + bb.y) * SCALE;
            }
            c2a<2>(qc, qahA, qalA);
#pragma unroll
            for (int nc = 0; nc < 4; nc++) {
                float2 bb = *(const float2*)(smf + 0 + 8*nc + 2*t);
                qc[nc*4+0] = (CB[nc*4+0] + bb.x) * SCALE;
                qc[nc*4+1] = (CB[nc*4+1] + bb.y) * SCALE;
                qc[nc*4+2] = (CB[nc*4+2] + bb.x) * SCALE;
                qc[nc*4+3] = (CB[nc*4+3] + bb.y) * SCALE;
            }
            c2a<2>(qc, qahB, qalB);
        }
        __syncwarp();

        // ---- S = Q@K^T, softmax, P frags (per batch) ----
        uint32_t pahA[4], palA[4], pahB[4], palB[4];
#pragma unroll
        for (int side = 0; side < 2; side++) {
            const unsigned short *kh = (side ? stgB : stgA) + KH;
            const unsigned short *kl = (side ? stgB : stgA) + KL;
            float s[8];
#pragma unroll
            for (int i2 = 0; i2 < 8; i2++) s[i2] = 0.f;
            if (side) gemm<2,2,36>(s, qahB, qalB, kh, kl, g, t);
            else      gemm<2,2,36>(s, qahA, qalA, kh, kl, g, t);

            float m0 = fmaxf(fmaxf(s[0], s[1]), fmaxf(s[4], s[5]));
            float m1 = fmaxf(fmaxf(s[2], s[3]), fmaxf(s[6], s[7]));
            m0 = fmaxf(m0, __shfl_xor_sync(0xffffffffu, m0, 1));
            m0 = fmaxf(m0, __shfl_xor_sync(0xffffffffu, m0, 2));
            m1 = fmaxf(m1, __shfl_xor_sync(0xffffffffu, m1, 1));
            m1 = fmaxf(m1, __shfl_xor_sync(0xffffffffu, m1, 2));
            s[0] = __expf(s[0] - m0); s[1] = __expf(s[1] - m0);
            s[4] = __expf(s[4] - m0); s[5] = __expf(s[5] - m0);
            s[2] = __expf(s[2] - m1); s[3] = __expf(s[3] - m1);
            s[6] = __expf(s[6] - m1); s[7] = __expf(s[7] - m1);
            float t0 = s[0] + s[1] + s[4] + s[5];
            float t1 = s[2] + s[3] + s[6] + s[7];
            t0 += __shfl_xor_sync(0xffffffffu, t0, 1);
            t0 += __shfl_xor_sync(0xffffffffu, t0, 2);
            t1 += __shfl_xor_sync(0xffffffffu, t1, 1);
            t1 += __shfl_xor_sync(0xffffffffu, t1, 2);
            float i0 = 1.f / t0, i1 = 1.f / t1;
            s[0] *= i0; s[1] *= i0; s[4] *= i0; s[5] *= i0;
            s[2] *= i1; s[3] *= i1; s[6] *= i1; s[7] *= i1;

            uint32_t *ph = side ? pahB : pahA;
            uint32_t *pl = side ? palB : palA;
            split2(s[0], s[1], ph[0], pl[0]);
            split2(s[2], s[3], ph[1], pl[1]);
            split2(s[4], s[5], ph[2], pl[2]);
            split2(s[6], s[7], ph[3], pl[3]);
        }

        // ---- ctx = P@V (per batch) ----
#pragma unroll
        for (int i2 = 0; i2 < 16; i2++) { CA[i2] = 0.f; CB[i2] = 0.f; }
        gemm<1,4,24>(CA, pahA, palA, stgA + VTH, stgA + VTL, g, t);
        gemm<1,4,24>(CB, pahB, palB, stgB + VTH, stgB + VTL, g, t);

        // ---- y = x + ctx@Wo + bo ----
        uint32_t cahA[8], calA[8], cahB[8], calB[8];
        c2a<2>(CA, cahA, calA);
        c2a<2>(CB, cahB, calB);
        float yvA[16], yvB[16];
#pragma unroll
        for (int i2 = 0; i2 < 16; i2++) { yvA[i2] = 0.f; yvB[i2] = 0.f; }
        gemm2<2,4,36>(yvA, yvB, cahA, calA, cahB, calB, sm16 + WOH, sm16 + WOL, g, t);
#pragma unroll
        for (int nc = 0; nc < 4; nc++) {
            float2 bb = *(const float2*)(smf + 96 + 8*nc + 2*t);
            yvA[nc*4+0] += xcA[nc*4+0] + bb.x;
            yvA[nc*4+1] += xcA[nc*4+1] + bb.y;
            yvA[nc*4+2] += xcA[nc*4+2] + bb.x;
            yvA[nc*4+3] += xcA[nc*4+3] + bb.y;
            yvB[nc*4+0] += xcB[nc*4+0] + bb.x;
            yvB[nc*4+1] += xcB[nc*4+1] + bb.y;
            yvB[nc*4+2] += xcB[nc*4+2] + bb.x;
            yvB[nc*4+3] += xcB[nc*4+3] + bb.y;
        }

        // ---- h = relu(y@W1 + b1) ----
        uint32_t yahA[8], yalA[8], yahB[8], yalB[8];
        c2a<2>(yvA, yahA, yalA);
        c2a<2>(yvB, yahB, yalB);
        float hbA[32], hbB[32];
#pragma unroll
        for (int i2 = 0; i2 < 32; i2++) { hbA[i2] = 0.f; hbB[i2] = 0.f; }
        gemm2<2,8,36>(hbA, hbB, yahA, yalA, yahB, yalB, sm16 + W1H, sm16 + W1L, g, t);
#pragma unroll
        for (int nc = 0; nc < 8; nc++) {
            float2 bb = *(const float2*)(smf + 128 + 8*nc + 2*t);
            hbA[nc*4+0] = fmaxf(hbA[nc*4+0] + bb.x, 0.f);
            hbA[nc*4+1] = fmaxf(hbA[nc*4+1] + bb.y, 0.f);
            hbA[nc*4+2] = fmaxf(hbA[nc*4+2] + bb.x, 0.f);
            hbA[nc*4+3] = fmaxf(hbA[nc*4+3] + bb.y, 0.f);
            hbB[nc*4+0] = fmaxf(hbB[nc*4+0] + bb.x, 0.f);
            hbB[nc*4+1] = fmaxf(hbB[nc*4+1] + bb.y, 0.f);
            hbB[nc*4+2] = fmaxf(hbB[nc*4+2] + bb.x, 0.f);
            hbB[nc*4+3] = fmaxf(hbB[nc*4+3] + bb.y, 0.f);
        }

        // ---- z = y + h@W2 + b2 ----
        uint32_t hahA[16], halA[16], hahB[16], halB[16];
        c2a<4>(hbA, hahA, halA);
        c2a<4>(hbB, hahB, halB);
        float zvA[16], zvB[16];
#pragma unroll
        for (int i2 = 0; i2 < 16; i2++) { zvA[i2] = 0.f; zvB[i2] = 0.f; }
        gemm2<4,4,72>(zvA, zvB, hahA, halA, hahB, halB, sm16 + W2H, sm16 + W2L, g, t);

        float2 *opA = (float2*)(out + b0 * 512);
#pragma unroll
        for (int nc = 0; nc < 4; nc++) {
            float2 bb = *(const float2*)(smf + 192 + 8*nc + 2*t);
            opA[g*16 + nc*4 + t]     = make_float2(zvA[nc*4+0] + yvA[nc*4+0] + bb.x,
                                                   zvA[nc*4+1] + yvA[nc*4+1] + bb.y);
            opA[(g+8)*16 + nc*4 + t] = make_float2(zvA[nc*4+2] + yvA[nc*4+2] + bb.x,
                                                   zvA[nc*4+3] + yvA[nc*4+3] + bb.y);
        }
        if (v1) {
            float2 *opB = (float2*)(out + b1s * 512);
#pragma unroll
            for (int nc = 0; nc < 4; nc++) {
                float2 bb = *(const float2*)(smf + 192 + 8*nc + 2*t);
                opB[g*16 + nc*4 + t]     = make_float2(zvB[nc*4+0] + yvB[nc*4+0] + bb.x,
                                                       zvB[nc*4+1] + yvB[nc*4+1] + bb.y);
                opB[(g+8)*16 + nc*4 + t] = make_float2(zvB[nc*4+2] + yvB[nc*4+2] + bb.x,
                                                       zvB[nc*4+3] + yvB[nc*4+3] + bb.y);
            }
        }
        __syncwarp();   // staging reuse barrier for next pair
    }
}

extern "C" void kernel_launch(void* const* d_in, const int* in_sizes, int n_in,
                              void* d_out, int out_size)
{
    const float* x  = (const float*)d_in[0];
    const float* Wq = (const float*)d_in[1];
    const float* bq = (const float*)d_in[2];
    const float* Wk = (const float*)d_in[3];
    const float* bk = (const float*)d_in[4];
    const float* Wv = (const float*)d_in[5];
    const float* bv = (const float*)d_in[6];
    const float* Wo = (const float*)d_in[7];
    const float* bo = (const float*)d_in[8];
    const float* W1 = (const float*)d_in[9];
    const float* b1 = (const float*)d_in[10];
    const float* W2 = (const float*)d_in[11];
    const float* b2 = (const float*)d_in[12];
    float* out = (float*)d_out;

    const int B = in_sizes[0] / 512;                                    // 65536
    const int blocks = (B + BATCHES_PER_BLOCK - 1) / BATCHES_PER_BLOCK; // 2048

    cudaFuncSetAttribute(tinyformer_tc_kernel,
                         cudaFuncAttributeMaxDynamicSharedMemorySize, SMEM_BYTES);
    tinyformer_tc_kernel<<<blocks, THREADS, SMEM_BYTES>>>(x, Wq, bq, Wk, bk, Wv, bv,
                                                          Wo, bo, W1, b1, W2, b2, out, B);
}

// round 10
// speedup vs baseline: 1.1212x; 1.1212x over previous
#include <cuda_runtime.h>
#include <cuda_bf16.h>
#include <cstdint>

// ---------------------------------------------------------------------------
// TinyFormerEncoder R9: R8 (batch-paired split-precision bf16 mma) with
// compacted per-warp staging (K stride 34, vT stride 20) so THREE 128-thread
// blocks fit per SM: 12 warps/SM (vs 8) to hide mma dependency latency.
// Weight LDS stays halved via batch pairing.
// ---------------------------------------------------------------------------

namespace {
constexpr int THREADS = 128;          // 4 warps
constexpr int NB = 8;                 // batches per warp (4 pairs)
constexpr int BATCHES_PER_BLOCK = 4 * NB;  // 32

// ushort (bf16) offsets in dynamic smem
constexpr int WQH = 0,     WQL = 1152;
constexpr int WKH = 2304,  WKL = 3456;
constexpr int WVH = 4608,  WVL = 5760;
constexpr int WOH = 6912,  WOL = 8064;     // 32x32 mats, row stride 36
constexpr int W1H = 9216,  W1L = 11520;    // 64 rows x stride 36
constexpr int W2H = 13824, W2L = 16128;    // 32 rows x stride 72
constexpr int BIASU  = 18432;              // float bias block starts here
constexpr int STAGEU = 18880;              // per-warp staging base (ushort)
// staging strides (compacted vs R8)
constexpr int KS = 34;                     // K row stride (ushorts)
constexpr int VS = 20;                     // vT row stride (ushorts)
constexpr int KH = 0, KL = 16 * KS;        // 0, 544
constexpr int VTH = 2 * 16 * KS;           // 1088
constexpr int VTL = VTH + 32 * VS;         // 1728
constexpr int BATCH_STAGE = VTL + 32 * VS; // 2368 ushorts per batch slot
constexpr int WARP_STAGE  = 2 * BATCH_STAGE;
constexpr int SMEM_BYTES = (STAGEU + 4 * WARP_STAGE) * 2;  // 75648
constexpr float SCALE = 0.17677669529663687f;  // 1/sqrt(32)
}

__device__ __forceinline__ uint32_t packbf(float lo, float hi) {
    uint32_t r;
    asm("cvt.rn.bf16x2.f32 %0, %1, %2;" : "=r"(r) : "f"(hi), "f"(lo));
    return r;
}
__device__ __forceinline__ float lo2f(uint32_t v) { return __uint_as_float(v << 16); }
__device__ __forceinline__ float hi2f(uint32_t v) { return __uint_as_float(v & 0xffff0000u); }

__device__ __forceinline__ void split2(float e0, float e1, uint32_t &h, uint32_t &l) {
    h = packbf(e0, e1);
    l = packbf(e0 - lo2f(h), e1 - hi2f(h));
}

__device__ __forceinline__ void mma16816(float &c0, float &c1, float &c2, float &c3,
                                         uint32_t a0, uint32_t a1, uint32_t a2, uint32_t a3,
                                         uint32_t b0, uint32_t b1) {
    asm("mma.sync.aligned.m16n8k16.row.col.f32.bf16.bf16.f32 "
        "{%0,%1,%2,%3}, {%4,%5,%6,%7}, {%8,%9}, {%0,%1,%2,%3};"
        : "+f"(c0), "+f"(c1), "+f"(c2), "+f"(c3)
        : "r"(a0), "r"(a1), "r"(a2), "r"(a3), "r"(b0), "r"(b1));
}

__device__ __forceinline__ void mma3(float *c, const uint32_t *ah, const uint32_t *al,
                                     uint32_t bh0, uint32_t bh1, uint32_t bl0, uint32_t bl1) {
    mma16816(c[0],c[1],c[2],c[3], ah[0],ah[1],ah[2],ah[3], bh0,bh1);
    mma16816(c[0],c[1],c[2],c[3], ah[0],ah[1],ah[2],ah[3], bl0,bl1);
    mma16816(c[0],c[1],c[2],c[3], al[0],al[1],al[2],al[3], bh0,bh1);
}

template <int KCH>
__device__ __forceinline__ void c2a(const float *C, uint32_t *ah, uint32_t *al) {
#pragma unroll
    for (int kc = 0; kc < KCH; kc++) {
        split2(C[8*kc+0], C[8*kc+1], ah[kc*4+0], al[kc*4+0]);
        split2(C[8*kc+2], C[8*kc+3], ah[kc*4+1], al[kc*4+1]);
        split2(C[8*kc+4], C[8*kc+5], ah[kc*4+2], al[kc*4+2]);
        split2(C[8*kc+6], C[8*kc+7], ah[kc*4+3], al[kc*4+3]);
    }
}

template <int KCH, int NCH, int RS>
__device__ __forceinline__ void gemm(float *C, const uint32_t *ah, const uint32_t *al,
                                     const unsigned short *wh, const unsigned short *wl,
                                     int g, int t) {
#pragma unroll
    for (int j = 0; j < NCH; j++) {
#pragma unroll
        for (int kc = 0; kc < KCH; kc++) {
            const unsigned short *ph = wh + (8*j + g)*RS + kc*16 + 2*t;
            const unsigned short *pl = wl + (8*j + g)*RS + kc*16 + 2*t;
            uint32_t bh0 = *(const uint32_t*)ph, bh1 = *(const uint32_t*)(ph + 8);
            uint32_t bl0 = *(const uint32_t*)pl, bl1 = *(const uint32_t*)(pl + 8);
            mma3(C + j*4, ah + kc*4, al + kc*4, bh0, bh1, bl0, bl1);
        }
    }
}

template <int KCH, int NCH, int RS>
__device__ __forceinline__ void gemm2(float *CA, float *CB,
                                      const uint32_t *ahA, const uint32_t *alA,
                                      const uint32_t *ahB, const uint32_t *alB,
                                      const unsigned short *wh, const unsigned short *wl,
                                      int g, int t) {
#pragma unroll
    for (int j = 0; j < NCH; j++) {
#pragma unroll
        for (int kc = 0; kc < KCH; kc++) {
            const unsigned short *ph = wh + (8*j + g)*RS + kc*16 + 2*t;
            const unsigned short *pl = wl + (8*j + g)*RS + kc*16 + 2*t;
            uint32_t bh0 = *(const uint32_t*)ph, bh1 = *(const uint32_t*)(ph + 8);
            uint32_t bl0 = *(const uint32_t*)pl, bl1 = *(const uint32_t*)(pl + 8);
            mma3(CA + j*4, ahA + kc*4, alA + kc*4, bh0, bh1, bl0, bl1);
            mma3(CB + j*4, ahB + kc*4, alB + kc*4, bh0, bh1, bl0, bl1);
        }
    }
}

__global__ void __launch_bounds__(THREADS, 3)
tinyformer_tc_kernel(const float *__restrict__ x,
                     const float *__restrict__ Wq, const float *__restrict__ bq,
                     const float *__restrict__ Wk, const float *__restrict__ bk,
                     const float *__restrict__ Wv, const float *__restrict__ bv,
                     const float *__restrict__ Wo, const float *__restrict__ bo,
                     const float *__restrict__ W1, const float *__restrict__ b1,
                     const float *__restrict__ W2, const float *__restrict__ b2,
                     float *__restrict__ out, int B)
{
    extern __shared__ unsigned short sm16[];
    float *smf = (float*)(sm16 + BIASU);
    const int tid = threadIdx.x;

    // ---- stage weights: transpose + split into bf16 hi/lo planes ----
    for (int i = tid; i < 1024; i += THREADS) {
        int d = i >> 5, j = i & 31;
        int o = j*36 + d;
        {   float v = Wq[i]; uint32_t p = packbf(v, 0.f);
            sm16[WQH + o] = (unsigned short)p;
            sm16[WQL + o] = (unsigned short)packbf(v - lo2f(p), 0.f); }
        {   float v = Wk[i]; uint32_t p = packbf(v, 0.f);
            sm16[WKH + o] = (unsigned short)p;
            sm16[WKL + o] = (unsigned short)packbf(v - lo2f(p), 0.f); }
        {   float v = Wv[i]; uint32_t p = packbf(v, 0.f);
            sm16[WVH + o] = (unsigned short)p;
            sm16[WVL + o] = (unsigned short)packbf(v - lo2f(p), 0.f); }
        {   float v = Wo[i]; uint32_t p = packbf(v, 0.f);
            sm16[WOH + o] = (unsigned short)p;
            sm16[WOL + o] = (unsigned short)packbf(v - lo2f(p), 0.f); }
    }
    for (int i = tid; i < 2048; i += THREADS) {
        {   int d = i >> 6, j = i & 63;
            float v = W1[i]; uint32_t p = packbf(v, 0.f);
            sm16[W1H + j*36 + d] = (unsigned short)p;
            sm16[W1L + j*36 + d] = (unsigned short)packbf(v - lo2f(p), 0.f); }
        {   int h = i >> 5, j = i & 31;
            float v = W2[i]; uint32_t p = packbf(v, 0.f);
            sm16[W2H + j*72 + h] = (unsigned short)p;
            sm16[W2L + j*72 + h] = (unsigned short)packbf(v - lo2f(p), 0.f); }
    }
    if (tid < 32) {
        smf[0   + tid] = bq[tid]; smf[32 + tid] = bk[tid]; smf[64 + tid] = bv[tid];
        smf[96  + tid] = bo[tid]; smf[192 + tid] = b2[tid];
    }
    if (tid < 64) smf[128 + tid] = b1[tid];
    __syncthreads();

    const int warp = tid >> 5, lane = tid & 31;
    const int g = lane >> 2, t = lane & 3;
    unsigned short *stgA = sm16 + STAGEU + warp * WARP_STAGE;
    unsigned short *stgB = stgA + BATCH_STAGE;

    for (int it = 0; it < NB/2; it++) {
        size_t b0 = (size_t)blockIdx.x * BATCHES_PER_BLOCK + warp * NB + 2*it;
        if (b0 >= (size_t)B) continue;           // warp-uniform
        size_t b1s = b0 + 1;
        const bool v1 = b1s < (size_t)B;
        if (!v1) b1s = b0;

        // ---- x (both batches) in C-fragment layout, fp32 ----
        const float2 *xpA = (const float2*)(x + b0 * 512);
        const float2 *xpB = (const float2*)(x + b1s * 512);
        float xcA[16], xcB[16];
#pragma unroll
        for (int nc = 0; nc < 4; nc++) {
            float2 p0 = xpA[g*16 + nc*4 + t], p1 = xpA[(g+8)*16 + nc*4 + t];
            xcA[nc*4+0] = p0.x; xcA[nc*4+1] = p0.y;
            xcA[nc*4+2] = p1.x; xcA[nc*4+3] = p1.y;
            float2 q0 = xpB[g*16 + nc*4 + t], q1 = xpB[(g+8)*16 + nc*4 + t];
            xcB[nc*4+0] = q0.x; xcB[nc*4+1] = q0.y;
            xcB[nc*4+2] = q1.x; xcB[nc*4+3] = q1.y;
        }
        uint32_t xahA[8], xalA[8], xahB[8], xalB[8];
        c2a<2>(xcA, xahA, xalA);
        c2a<2>(xcB, xahB, xalB);

        float CA[16], CB[16];

        // ---- K (both) -> split-stored row-major (stride KS) ----
#pragma unroll
        for (int i2 = 0; i2 < 16; i2++) { CA[i2] = 0.f; CB[i2] = 0.f; }
        gemm2<2,4,36>(CA, CB, xahA, xalA, xahB, xalB, sm16 + WKH, sm16 + WKL, g, t);
#pragma unroll
        for (int nc = 0; nc < 4; nc++) {
            float2 bb = *(const float2*)(smf + 32 + 8*nc + 2*t);
            int c0 = nc*8 + 2*t;
            uint32_t h0, l0, h1, l1;
            split2(CA[nc*4+0] + bb.x, CA[nc*4+1] + bb.y, h0, l0);
            split2(CA[nc*4+2] + bb.x, CA[nc*4+3] + bb.y, h1, l1);
            *(uint32_t*)(stgA + KH + g*KS     + c0) = h0;
            *(uint32_t*)(stgA + KL + g*KS     + c0) = l0;
            *(uint32_t*)(stgA + KH + (g+8)*KS + c0) = h1;
            *(uint32_t*)(stgA + KL + (g+8)*KS + c0) = l1;
            split2(CB[nc*4+0] + bb.x, CB[nc*4+1] + bb.y, h0, l0);
            split2(CB[nc*4+2] + bb.x, CB[nc*4+3] + bb.y, h1, l1);
            *(uint32_t*)(stgB + KH + g*KS     + c0) = h0;
            *(uint32_t*)(stgB + KL + g*KS     + c0) = l0;
            *(uint32_t*)(stgB + KH + (g+8)*KS + c0) = h1;
            *(uint32_t*)(stgB + KL + (g+8)*KS + c0) = l1;
        }

        // ---- V (both) -> split-stored TRANSPOSED (stride VS) ----
#pragma unroll
        for (int i2 = 0; i2 < 16; i2++) { CA[i2] = 0.f; CB[i2] = 0.f; }
        gemm2<2,4,36>(CA, CB, xahA, xalA, xahB, xalB, sm16 + WVH, sm16 + WVL, g, t);
#pragma unroll
        for (int nc = 0; nc < 4; nc++) {
            float2 bb = *(const float2*)(smf + 64 + 8*nc + 2*t);
            int col0 = 8*nc + 2*t;
#pragma unroll
            for (int m = 0; m < 4; m++) {
                int col = col0 + (m & 1);
                int row = (m < 2) ? g : g + 8;
                float eA = CA[nc*4+m] + ((m & 1) ? bb.y : bb.x);
                uint32_t pA = packbf(eA, 0.f);
                stgA[VTH + col*VS + row] = (unsigned short)pA;
                stgA[VTL + col*VS + row] = (unsigned short)packbf(eA - lo2f(pA), 0.f);
                float eB = CB[nc*4+m] + ((m & 1) ? bb.y : bb.x);
                uint32_t pB = packbf(eB, 0.f);
                stgB[VTH + col*VS + row] = (unsigned short)pB;
                stgB[VTL + col*VS + row] = (unsigned short)packbf(eB - lo2f(pB), 0.f);
            }
        }

        // ---- Q (both) -> scaled A-fragments ----
#pragma unroll
        for (int i2 = 0; i2 < 16; i2++) { CA[i2] = 0.f; CB[i2] = 0.f; }
        gemm2<2,4,36>(CA, CB, xahA, xalA, xahB, xalB, sm16 + WQH, sm16 + WQL, g, t);
        uint32_t qahA[8], qalA[8], qahB[8], qalB[8];
        {
            float qc[16];
#pragma unroll
            for (int nc = 0; nc < 4; nc++) {
                float2 bb = *(const float2*)(smf + 0 + 8*nc + 2*t);
                qc[nc*4+0] = (CA[nc*4+0] + bb.x) * SCALE;
                qc[nc*4+1] = (CA[nc*4+1] + bb.y) * SCALE;
                qc[nc*4+2] = (CA[nc*4+2] + bb.x) * SCALE;
                qc[nc*4+3] = (CA[nc*4+3] + bb.y) * SCALE;
            }
            c2a<2>(qc, qahA, qalA);
#pragma unroll
            for (int nc = 0; nc < 4; nc++) {
                float2 bb = *(const float2*)(smf + 0 + 8*nc + 2*t);
                qc[nc*4+0] = (CB[nc*4+0] + bb.x) * SCALE;
                qc[nc*4+1] = (CB[nc*4+1] + bb.y) * SCALE;
                qc[nc*4+2] = (CB[nc*4+2] + bb.x) * SCALE;
                qc[nc*4+3] = (CB[nc*4+3] + bb.y) * SCALE;
            }
            c2a<2>(qc, qahB, qalB);
        }
        __syncwarp();

        // ---- S = Q@K^T, softmax, P frags (per batch) ----
        uint32_t pahA[4], palA[4], pahB[4], palB[4];
#pragma unroll
        for (int side = 0; side < 2; side++) {
            const unsigned short *kh = (side ? stgB : stgA) + KH;
            const unsigned short *kl = (side ? stgB : stgA) + KL;
            float s[8];
#pragma unroll
            for (int i2 = 0; i2 < 8; i2++) s[i2] = 0.f;
            if (side) gemm<2,2,KS>(s, qahB, qalB, kh, kl, g, t);
            else      gemm<2,2,KS>(s, qahA, qalA, kh, kl, g, t);

            float m0 = fmaxf(fmaxf(s[0], s[1]), fmaxf(s[4], s[5]));
            float m1 = fmaxf(fmaxf(s[2], s[3]), fmaxf(s[6], s[7]));
            m0 = fmaxf(m0, __shfl_xor_sync(0xffffffffu, m0, 1));
            m0 = fmaxf(m0, __shfl_xor_sync(0xffffffffu, m0, 2));
            m1 = fmaxf(m1, __shfl_xor_sync(0xffffffffu, m1, 1));
            m1 = fmaxf(m1, __shfl_xor_sync(0xffffffffu, m1, 2));
            s[0] = __expf(s[0] - m0); s[1] = __expf(s[1] - m0);
            s[4] = __expf(s[4] - m0); s[5] = __expf(s[5] - m0);
            s[2] = __expf(s[2] - m1); s[3] = __expf(s[3] - m1);
            s[6] = __expf(s[6] - m1); s[7] = __expf(s[7] - m1);
            float t0 = s[0] + s[1] + s[4] + s[5];
            float t1 = s[2] + s[3] + s[6] + s[7];
            t0 += __shfl_xor_sync(0xffffffffu, t0, 1);
            t0 += __shfl_xor_sync(0xffffffffu, t0, 2);
            t1 += __shfl_xor_sync(0xffffffffu, t1, 1);
            t1 += __shfl_xor_sync(0xffffffffu, t1, 2);
            float i0 = 1.f / t0, i1 = 1.f / t1;
            s[0] *= i0; s[1] *= i0; s[4] *= i0; s[5] *= i0;
            s[2] *= i1; s[3] *= i1; s[6] *= i1; s[7] *= i1;

            uint32_t *ph = side ? pahB : pahA;
            uint32_t *pl = side ? palB : palA;
            split2(s[0], s[1], ph[0], pl[0]);
            split2(s[2], s[3], ph[1], pl[1]);
            split2(s[4], s[5], ph[2], pl[2]);
            split2(s[6], s[7], ph[3], pl[3]);
        }

        // ---- ctx = P@V (per batch) ----
#pragma unroll
        for (int i2 = 0; i2 < 16; i2++) { CA[i2] = 0.f; CB[i2] = 0.f; }
        gemm<1,4,VS>(CA, pahA, palA, stgA + VTH, stgA + VTL, g, t);
        gemm<1,4,VS>(CB, pahB, palB, stgB + VTH, stgB + VTL, g, t);

        // ---- y = x + ctx@Wo + bo ----
        uint32_t cahA[8], calA[8], cahB[8], calB[8];
        c2a<2>(CA, cahA, calA);
        c2a<2>(CB, cahB, calB);
        float yvA[16], yvB[16];
#pragma unroll
        for (int i2 = 0; i2 < 16; i2++) { yvA[i2] = 0.f; yvB[i2] = 0.f; }
        gemm2<2,4,36>(yvA, yvB, cahA, calA, cahB, calB, sm16 + WOH, sm16 + WOL, g, t);
#pragma unroll
        for (int nc = 0; nc < 4; nc++) {
            float2 bb = *(const float2*)(smf + 96 + 8*nc + 2*t);
            yvA[nc*4+0] += xcA[nc*4+0] + bb.x;
            yvA[nc*4+1] += xcA[nc*4+1] + bb.y;
            yvA[nc*4+2] += xcA[nc*4+2] + bb.x;
            yvA[nc*4+3] += xcA[nc*4+3] + bb.y;
            yvB[nc*4+0] += xcB[nc*4+0] + bb.x;
            yvB[nc*4+1] += xcB[nc*4+1] + bb.y;
            yvB[nc*4+2] += xcB[nc*4+2] + bb.x;
            yvB[nc*4+3] += xcB[nc*4+3] + bb.y;
        }

        // ---- h = relu(y@W1 + b1) ----
        uint32_t yahA[8], yalA[8], yahB[8], yalB[8];
        c2a<2>(yvA, yahA, yalA);
        c2a<2>(yvB, yahB, yalB);
        float hbA[32], hbB[32];
#pragma unroll
        for (int i2 = 0; i2 < 32; i2++) { hbA[i2] = 0.f; hbB[i2] = 0.f; }
        gemm2<2,8,36>(hbA, hbB, yahA, yalA, yahB, yalB, sm16 + W1H, sm16 + W1L, g, t);
#pragma unroll
        for (int nc = 0; nc < 8; nc++) {
            float2 bb = *(const float2*)(smf + 128 + 8*nc + 2*t);
            hbA[nc*4+0] = fmaxf(hbA[nc*4+0] + bb.x, 0.f);
            hbA[nc*4+1] = fmaxf(hbA[nc*4+1] + bb.y, 0.f);
            hbA[nc*4+2] = fmaxf(hbA[nc*4+2] + bb.x, 0.f);
            hbA[nc*4+3] = fmaxf(hbA[nc*4+3] + bb.y, 0.f);
            hbB[nc*4+0] = fmaxf(hbB[nc*4+0] + bb.x, 0.f);
            hbB[nc*4+1] = fmaxf(hbB[nc*4+1] + bb.y, 0.f);
            hbB[nc*4+2] = fmaxf(hbB[nc*4+2] + bb.x, 0.f);
            hbB[nc*4+3] = fmaxf(hbB[nc*4+3] + bb.y, 0.f);
        }

        // ---- z = y + h@W2 + b2 ----
        uint32_t hahA[16], halA[16], hahB[16], halB[16];
        c2a<4>(hbA, hahA, halA);
        c2a<4>(hbB, hahB, halB);
        float zvA[16], zvB[16];
#pragma unroll
        for (int i2 = 0; i2 < 16; i2++) { zvA[i2] = 0.f; zvB[i2] = 0.f; }
        gemm2<4,4,72>(zvA, zvB, hahA, halA, hahB, halB, sm16 + W2H, sm16 + W2L, g, t);

        float2 *opA = (float2*)(out + b0 * 512);
#pragma unroll
        for (int nc = 0; nc < 4; nc++) {
            float2 bb = *(const float2*)(smf + 192 + 8*nc + 2*t);
            opA[g*16 + nc*4 + t]     = make_float2(zvA[nc*4+0] + yvA[nc*4+0] + bb.x,
                                                   zvA[nc*4+1] + yvA[nc*4+1] + bb.y);
            opA[(g+8)*16 + nc*4 + t] = make_float2(zvA[nc*4+2] + yvA[nc*4+2] + bb.x,
                                                   zvA[nc*4+3] + yvA[nc*4+3] + bb.y);
        }
        if (v1) {
            float2 *opB = (float2*)(out + b1s * 512);
#pragma unroll
            for (int nc = 0; nc < 4; nc++) {
                float2 bb = *(const float2*)(smf + 192 + 8*nc + 2*t);
                opB[g*16 + nc*4 + t]     = make_float2(zvB[nc*4+0] + yvB[nc*4+0] + bb.x,
                                                       zvB[nc*4+1] + yvB[nc*4+1] + bb.y);
                opB[(g+8)*16 + nc*4 + t] = make_float2(zvB[nc*4+2] + yvB[nc*4+2] + bb.x,
                                                       zvB[nc*4+3] + yvB[nc*4+3] + bb.y);
            }
        }
        __syncwarp();   // staging reuse barrier for next pair
    }
}

extern "C" void kernel_launch(void* const* d_in, const int* in_sizes, int n_in,
                              void* d_out, int out_size)
{
    const float* x  = (const float*)d_in[0];
    const float* Wq = (const float*)d_in[1];
    const float* bq = (const float*)d_in[2];
    const float* Wk = (const float*)d_in[3];
    const float* bk = (const float*)d_in[4];
    const float* Wv = (const float*)d_in[5];
    const float* bv = (const float*)d_in[6];
    const float* Wo = (const float*)d_in[7];
    const float* bo = (const float*)d_in[8];
    const float* W1 = (const float*)d_in[9];
    const float* b1 = (const float*)d_in[10];
    const float* W2 = (const float*)d_in[11];
    const float* b2 = (const float*)d_in[12];
    float* out = (float*)d_out;

    const int B = in_sizes[0] / 512;                                    // 65536
    const int blocks = (B + BATCHES_PER_BLOCK - 1) / BATCHES_PER_BLOCK; // 2048

    cudaFuncSetAttribute(tinyformer_tc_kernel,
                         cudaFuncAttributeMaxDynamicSharedMemorySize, SMEM_BYTES);
    tinyformer_tc_kernel<<<blocks, THREADS, SMEM_BYTES>>>(x, Wq, bq, Wk, bk, Wv, bv,
                                                          Wo, bo, W1, b1, W2, b2, out, B);
}

// round 11
// speedup vs baseline: 1.3821x; 1.2327x over previous
#include <cuda_runtime.h>
#include <cuda_fp16.h>
#include <cstdint>

// ---------------------------------------------------------------------------
// TinyFormerEncoder R10: fp16 2-term split for weight GEMMs.
// a = ah + al is an EXACT fp16 split; fp16 products accumulate exactly in
// fp32. So ah*bh + al*bh == a*bh exactly -> weight gemms need only the hi
// weight plane and 2 mma per logical mma (vs 3). Only error: weight rounding
// (~2^-11 RMS). Attention gemms (S, ctx) stay 3-term (split K/V staging) to
// keep softmax logits near-exact. Batch pairing + 12 warps/SM kept from R9.
// mma/batch: 216 -> 152; weight LDS halved; weight smem halved.
// ---------------------------------------------------------------------------

namespace {
constexpr int THREADS = 128;          // 4 warps
constexpr int NB = 8;                 // batches per warp (4 pairs)
constexpr int BATCHES_PER_BLOCK = 4 * NB;  // 32

// ushort (fp16) offsets in dynamic smem — hi weight planes only
constexpr int WQH = 0;                     // 32 x stride36
constexpr int WKH = 1152;
constexpr int WVH = 2304;
constexpr int WOH = 3456;
constexpr int W1H = 4608;                  // 64 x stride36
constexpr int W2H = 6912;                  // 32 x stride72
constexpr int BIASU  = 9216;               // 224 floats = 448 ushorts
constexpr int STAGEU = 9664;               // per-warp staging base
constexpr int KS = 34;                     // K row stride (ushorts)
constexpr int VS = 20;                     // vT row stride (ushorts)
constexpr int KH = 0, KL = 16 * KS;        // 0, 544
constexpr int VTH = 2 * 16 * KS;           // 1088
constexpr int VTL = VTH + 32 * VS;         // 1728
constexpr int BATCH_STAGE = VTL + 32 * VS; // 2368
constexpr int WARP_STAGE  = 2 * BATCH_STAGE;
constexpr int SMEM_BYTES = (STAGEU + 4 * WARP_STAGE) * 2;  // 57216
constexpr float SCALE = 0.17677669529663687f;  // 1/sqrt(32)
}

__device__ __forceinline__ uint32_t packh(float e0, float e1) {
    __half2 h = __float22half2_rn(make_float2(e0, e1));   // e0 -> low half
    return *(uint32_t*)&h;
}
__device__ __forceinline__ float2 unpackh(uint32_t v) {
    __half2 h = *(__half2*)&v;
    return __half22float2(h);
}
// exact fp16 split of a pair
__device__ __forceinline__ void split2(float e0, float e1, uint32_t &h, uint32_t &l) {
    h = packh(e0, e1);
    float2 b = unpackh(h);
    l = packh(e0 - b.x, e1 - b.y);
}
__device__ __forceinline__ unsigned short f2h(float v) {
    __half h = __float2half_rn(v);
    return *(unsigned short*)&h;
}

__device__ __forceinline__ void mma16816(float &c0, float &c1, float &c2, float &c3,
                                         uint32_t a0, uint32_t a1, uint32_t a2, uint32_t a3,
                                         uint32_t b0, uint32_t b1) {
    asm("mma.sync.aligned.m16n8k16.row.col.f32.f16.f16.f32 "
        "{%0,%1,%2,%3}, {%4,%5,%6,%7}, {%8,%9}, {%0,%1,%2,%3};"
        : "+f"(c0), "+f"(c1), "+f"(c2), "+f"(c3)
        : "r"(a0), "r"(a1), "r"(a2), "r"(a3), "r"(b0), "r"(b1));
}

// 3-term split mma (attention: split A x split B, drop lo*lo)
__device__ __forceinline__ void mma3(float *c, const uint32_t *ah, const uint32_t *al,
                                     uint32_t bh0, uint32_t bh1, uint32_t bl0, uint32_t bl1) {
    mma16816(c[0],c[1],c[2],c[3], ah[0],ah[1],ah[2],ah[3], bh0,bh1);
    mma16816(c[0],c[1],c[2],c[3], ah[0],ah[1],ah[2],ah[3], bl0,bl1);
    mma16816(c[0],c[1],c[2],c[3], al[0],al[1],al[2],al[3], bh0,bh1);
}
// 2-term exact-A mma (weight gemms: (ah+al) x bh == a x bh exactly)
__device__ __forceinline__ void mma2(float *c, const uint32_t *ah, const uint32_t *al,
                                     uint32_t b0, uint32_t b1) {
    mma16816(c[0],c[1],c[2],c[3], ah[0],ah[1],ah[2],ah[3], b0,b1);
    mma16816(c[0],c[1],c[2],c[3], al[0],al[1],al[2],al[3], b0,b1);
}

template <int KCH>
__device__ __forceinline__ void c2a(const float *C, uint32_t *ah, uint32_t *al) {
#pragma unroll
    for (int kc = 0; kc < KCH; kc++) {
        split2(C[8*kc+0], C[8*kc+1], ah[kc*4+0], al[kc*4+0]);
        split2(C[8*kc+2], C[8*kc+3], ah[kc*4+1], al[kc*4+1]);
        split2(C[8*kc+4], C[8*kc+5], ah[kc*4+2], al[kc*4+2]);
        split2(C[8*kc+6], C[8*kc+7], ah[kc*4+3], al[kc*4+3]);
    }
}

// 3-term single-batch gemm (attention)
template <int KCH, int NCH, int RS>
__device__ __forceinline__ void gemm(float *C, const uint32_t *ah, const uint32_t *al,
                                     const unsigned short *wh, const unsigned short *wl,
                                     int g, int t) {
#pragma unroll
    for (int j = 0; j < NCH; j++) {
#pragma unroll
        for (int kc = 0; kc < KCH; kc++) {
            const unsigned short *ph = wh + (8*j + g)*RS + kc*16 + 2*t;
            const unsigned short *pl = wl + (8*j + g)*RS + kc*16 + 2*t;
            uint32_t bh0 = *(const uint32_t*)ph, bh1 = *(const uint32_t*)(ph + 8);
            uint32_t bl0 = *(const uint32_t*)pl, bl1 = *(const uint32_t*)(pl + 8);
            mma3(C + j*4, ah + kc*4, al + kc*4, bh0, bh1, bl0, bl1);
        }
    }
}

// 2-term batch-paired gemm (weight gemms; hi plane only)
template <int KCH, int NCH, int RS>
__device__ __forceinline__ void gemm2w(float *CA, float *CB,
                                       const uint32_t *ahA, const uint32_t *alA,
                                       const uint32_t *ahB, const uint32_t *alB,
                                       const unsigned short *wh, int g, int t) {
#pragma unroll
    for (int j = 0; j < NCH; j++) {
#pragma unroll
        for (int kc = 0; kc < KCH; kc++) {
            const unsigned short *ph = wh + (8*j + g)*RS + kc*16 + 2*t;
            uint32_t b0 = *(const uint32_t*)ph, b1 = *(const uint32_t*)(ph + 8);
            mma2(CA + j*4, ahA + kc*4, alA + kc*4, b0, b1);
            mma2(CB + j*4, ahB + kc*4, alB + kc*4, b0, b1);
        }
    }
}

__global__ void __launch_bounds__(THREADS, 3)
tinyformer_tc_kernel(const float *__restrict__ x,
                     const float *__restrict__ Wq, const float *__restrict__ bq,
                     const float *__restrict__ Wk, const float *__restrict__ bk,
                     const float *__restrict__ Wv, const float *__restrict__ bv,
                     const float *__restrict__ Wo, const float *__restrict__ bo,
                     const float *__restrict__ W1, const float *__restrict__ b1,
                     const float *__restrict__ W2, const float *__restrict__ b2,
                     float *__restrict__ out, int B)
{
    extern __shared__ unsigned short sm16[];
    float *smf = (float*)(sm16 + BIASU);
    const int tid = threadIdx.x;

    // ---- stage weights: transpose to fp16 hi planes ----
    for (int i = tid; i < 1024; i += THREADS) {
        int d = i >> 5, j = i & 31;
        int o = j*36 + d;
        sm16[WQH + o] = f2h(Wq[i]);
        sm16[WKH + o] = f2h(Wk[i]);
        sm16[WVH + o] = f2h(Wv[i]);
        sm16[WOH + o] = f2h(Wo[i]);
    }
    for (int i = tid; i < 2048; i += THREADS) {
        {   int d = i >> 6, j = i & 63;
            sm16[W1H + j*36 + d] = f2h(W1[i]); }
        {   int h = i >> 5, j = i & 31;
            sm16[W2H + j*72 + h] = f2h(W2[i]); }
    }
    if (tid < 32) {
        smf[0   + tid] = bq[tid]; smf[32 + tid] = bk[tid]; smf[64 + tid] = bv[tid];
        smf[96  + tid] = bo[tid]; smf[192 + tid] = b2[tid];
    }
    if (tid < 64) smf[128 + tid] = b1[tid];
    __syncthreads();

    const int warp = tid >> 5, lane = tid & 31;
    const int g = lane >> 2, t = lane & 3;
    unsigned short *stgA = sm16 + STAGEU + warp * WARP_STAGE;
    unsigned short *stgB = stgA + BATCH_STAGE;

    for (int it = 0; it < NB/2; it++) {
        size_t b0 = (size_t)blockIdx.x * BATCHES_PER_BLOCK + warp * NB + 2*it;
        if (b0 >= (size_t)B) continue;           // warp-uniform
        size_t b1s = b0 + 1;
        const bool v1 = b1s < (size_t)B;
        if (!v1) b1s = b0;

        // ---- x (both batches) in C-fragment layout, fp32 ----
        const float2 *xpA = (const float2*)(x + b0 * 512);
        const float2 *xpB = (const float2*)(x + b1s * 512);
        float xcA[16], xcB[16];
#pragma unroll
        for (int nc = 0; nc < 4; nc++) {
            float2 p0 = xpA[g*16 + nc*4 + t], p1 = xpA[(g+8)*16 + nc*4 + t];
            xcA[nc*4+0] = p0.x; xcA[nc*4+1] = p0.y;
            xcA[nc*4+2] = p1.x; xcA[nc*4+3] = p1.y;
            float2 q0 = xpB[g*16 + nc*4 + t], q1 = xpB[(g+8)*16 + nc*4 + t];
            xcB[nc*4+0] = q0.x; xcB[nc*4+1] = q0.y;
            xcB[nc*4+2] = q1.x; xcB[nc*4+3] = q1.y;
        }
        uint32_t xahA[8], xalA[8], xahB[8], xalB[8];
        c2a<2>(xcA, xahA, xalA);
        c2a<2>(xcB, xahB, xalB);

        float CA[16], CB[16];

        // ---- K (both) -> SPLIT-stored row-major (attention is 3-term) ----
#pragma unroll
        for (int i2 = 0; i2 < 16; i2++) { CA[i2] = 0.f; CB[i2] = 0.f; }
        gemm2w<2,4,36>(CA, CB, xahA, xalA, xahB, xalB, sm16 + WKH, g, t);
#pragma unroll
        for (int nc = 0; nc < 4; nc++) {
            float2 bb = *(const float2*)(smf + 32 + 8*nc + 2*t);
            int c0 = nc*8 + 2*t;
            uint32_t h0, l0, h1, l1;
            split2(CA[nc*4+0] + bb.x, CA[nc*4+1] + bb.y, h0, l0);
            split2(CA[nc*4+2] + bb.x, CA[nc*4+3] + bb.y, h1, l1);
            *(uint32_t*)(stgA + KH + g*KS     + c0) = h0;
            *(uint32_t*)(stgA + KL + g*KS     + c0) = l0;
            *(uint32_t*)(stgA + KH + (g+8)*KS + c0) = h1;
            *(uint32_t*)(stgA + KL + (g+8)*KS + c0) = l1;
            split2(CB[nc*4+0] + bb.x, CB[nc*4+1] + bb.y, h0, l0);
            split2(CB[nc*4+2] + bb.x, CB[nc*4+3] + bb.y, h1, l1);
            *(uint32_t*)(stgB + KH + g*KS     + c0) = h0;
            *(uint32_t*)(stgB + KL + g*KS     + c0) = l0;
            *(uint32_t*)(stgB + KH + (g+8)*KS + c0) = h1;
            *(uint32_t*)(stgB + KL + (g+8)*KS + c0) = l1;
        }

        // ---- V (both) -> SPLIT-stored TRANSPOSED ----
#pragma unroll
        for (int i2 = 0; i2 < 16; i2++) { CA[i2] = 0.f; CB[i2] = 0.f; }
        gemm2w<2,4,36>(CA, CB, xahA, xalA, xahB, xalB, sm16 + WVH, g, t);
#pragma unroll
        for (int nc = 0; nc < 4; nc++) {
            float2 bb = *(const float2*)(smf + 64 + 8*nc + 2*t);
            int col0 = 8*nc + 2*t;
#pragma unroll
            for (int m = 0; m < 4; m++) {
                int col = col0 + (m & 1);
                int row = (m < 2) ? g : g + 8;
                float eA = CA[nc*4+m] + ((m & 1) ? bb.y : bb.x);
                unsigned short hA = f2h(eA);
                __half hv = *(__half*)&hA;
                stgA[VTH + col*VS + row] = hA;
                stgA[VTL + col*VS + row] = f2h(eA - __half2float(hv));
                float eB = CB[nc*4+m] + ((m & 1) ? bb.y : bb.x);
                unsigned short hB = f2h(eB);
                __half hv2 = *(__half*)&hB;
                stgB[VTH + col*VS + row] = hB;
                stgB[VTL + col*VS + row] = f2h(eB - __half2float(hv2));
            }
        }

        // ---- Q (both) -> scaled A-fragments ----
#pragma unroll
        for (int i2 = 0; i2 < 16; i2++) { CA[i2] = 0.f; CB[i2] = 0.f; }
        gemm2w<2,4,36>(CA, CB, xahA, xalA, xahB, xalB, sm16 + WQH, g, t);
        uint32_t qahA[8], qalA[8], qahB[8], qalB[8];
        {
            float qc[16];
#pragma unroll
            for (int nc = 0; nc < 4; nc++) {
                float2 bb = *(const float2*)(smf + 0 + 8*nc + 2*t);
                qc[nc*4+0] = (CA[nc*4+0] + bb.x) * SCALE;
                qc[nc*4+1] = (CA[nc*4+1] + bb.y) * SCALE;
                qc[nc*4+2] = (CA[nc*4+2] + bb.x) * SCALE;
                qc[nc*4+3] = (CA[nc*4+3] + bb.y) * SCALE;
            }
            c2a<2>(qc, qahA, qalA);
#pragma unroll
            for (int nc = 0; nc < 4; nc++) {
                float2 bb = *(const float2*)(smf + 0 + 8*nc + 2*t);
                qc[nc*4+0] = (CB[nc*4+0] + bb.x) * SCALE;
                qc[nc*4+1] = (CB[nc*4+1] + bb.y) * SCALE;
                qc[nc*4+2] = (CB[nc*4+2] + bb.x) * SCALE;
                qc[nc*4+3] = (CB[nc*4+3] + bb.y) * SCALE;
            }
            c2a<2>(qc, qahB, qalB);
        }
        __syncwarp();

        // ---- S = Q@K^T (3-term), softmax, P frags (per batch) ----
        uint32_t pahA[4], palA[4], pahB[4], palB[4];
#pragma unroll
        for (int side = 0; side < 2; side++) {
            const unsigned short *kh = (side ? stgB : stgA) + KH;
            const unsigned short *kl = (side ? stgB : stgA) + KL;
            float s[8];
#pragma unroll
            for (int i2 = 0; i2 < 8; i2++) s[i2] = 0.f;
            if (side) gemm<2,2,KS>(s, qahB, qalB, kh, kl, g, t);
            else      gemm<2,2,KS>(s, qahA, qalA, kh, kl, g, t);

            float m0 = fmaxf(fmaxf(s[0], s[1]), fmaxf(s[4], s[5]));
            float m1 = fmaxf(fmaxf(s[2], s[3]), fmaxf(s[6], s[7]));
            m0 = fmaxf(m0, __shfl_xor_sync(0xffffffffu, m0, 1));
            m0 = fmaxf(m0, __shfl_xor_sync(0xffffffffu, m0, 2));
            m1 = fmaxf(m1, __shfl_xor_sync(0xffffffffu, m1, 1));
            m1 = fmaxf(m1, __shfl_xor_sync(0xffffffffu, m1, 2));
            s[0] = __expf(s[0] - m0); s[1] = __expf(s[1] - m0);
            s[4] = __expf(s[4] - m0); s[5] = __expf(s[5] - m0);
            s[2] = __expf(s[2] - m1); s[3] = __expf(s[3] - m1);
            s[6] = __expf(s[6] - m1); s[7] = __expf(s[7] - m1);
            float t0 = s[0] + s[1] + s[4] + s[5];
            float t1 = s[2] + s[3] + s[6] + s[7];
            t0 += __shfl_xor_sync(0xffffffffu, t0, 1);
            t0 += __shfl_xor_sync(0xffffffffu, t0, 2);
            t1 += __shfl_xor_sync(0xffffffffu, t1, 1);
            t1 += __shfl_xor_sync(0xffffffffu, t1, 2);
            float i0 = 1.f / t0, i1 = 1.f / t1;
            s[0] *= i0; s[1] *= i0; s[4] *= i0; s[5] *= i0;
            s[2] *= i1; s[3] *= i1; s[6] *= i1; s[7] *= i1;

            uint32_t *ph = side ? pahB : pahA;
            uint32_t *pl = side ? palB : palA;
            split2(s[0], s[1], ph[0], pl[0]);
            split2(s[2], s[3], ph[1], pl[1]);
            split2(s[4], s[5], ph[2], pl[2]);
            split2(s[6], s[7], ph[3], pl[3]);
        }

        // ---- ctx = P@V (3-term, per batch) ----
#pragma unroll
        for (int i2 = 0; i2 < 16; i2++) { CA[i2] = 0.f; CB[i2] = 0.f; }
        gemm<1,4,VS>(CA, pahA, palA, stgA + VTH, stgA + VTL, g, t);
        gemm<1,4,VS>(CB, pahB, palB, stgB + VTH, stgB + VTL, g, t);

        // ---- y = x + ctx@Wo + bo ----
        uint32_t cahA[8], calA[8], cahB[8], calB[8];
        c2a<2>(CA, cahA, calA);
        c2a<2>(CB, cahB, calB);
        float yvA[16], yvB[16];
#pragma unroll
        for (int i2 = 0; i2 < 16; i2++) { yvA[i2] = 0.f; yvB[i2] = 0.f; }
        gemm2w<2,4,36>(yvA, yvB, cahA, calA, cahB, calB, sm16 + WOH, g, t);
#pragma unroll
        for (int nc = 0; nc < 4; nc++) {
            float2 bb = *(const float2*)(smf + 96 + 8*nc + 2*t);
            yvA[nc*4+0] += xcA[nc*4+0] + bb.x;
            yvA[nc*4+1] += xcA[nc*4+1] + bb.y;
            yvA[nc*4+2] += xcA[nc*4+2] + bb.x;
            yvA[nc*4+3] += xcA[nc*4+3] + bb.y;
            yvB[nc*4+0] += xcB[nc*4+0] + bb.x;
            yvB[nc*4+1] += xcB[nc*4+1] + bb.y;
            yvB[nc*4+2] += xcB[nc*4+2] + bb.x;
            yvB[nc*4+3] += xcB[nc*4+3] + bb.y;
        }

        // ---- h = relu(y@W1 + b1) ----
        uint32_t yahA[8], yalA[8], yahB[8], yalB[8];
        c2a<2>(yvA, yahA, yalA);
        c2a<2>(yvB, yahB, yalB);
        float hbA[32], hbB[32];
#pragma unroll
        for (int i2 = 0; i2 < 32; i2++) { hbA[i2] = 0.f; hbB[i2] = 0.f; }
        gemm2w<2,8,36>(hbA, hbB, yahA, yalA, yahB, yalB, sm16 + W1H, g, t);
#pragma unroll
        for (int nc = 0; nc < 8; nc++) {
            float2 bb = *(const float2*)(smf + 128 + 8*nc + 2*t);
            hbA[nc*4+0] = fmaxf(hbA[nc*4+0] + bb.x, 0.f);
            hbA[nc*4+1] = fmaxf(hbA[nc*4+1] + bb.y, 0.f);
            hbA[nc*4+2] = fmaxf(hbA[nc*4+2] + bb.x, 0.f);
            hbA[nc*4+3] = fmaxf(hbA[nc*4+3] + bb.y, 0.f);
            hbB[nc*4+0] = fmaxf(hbB[nc*4+0] + bb.x, 0.f);
            hbB[nc*4+1] = fmaxf(hbB[nc*4+1] + bb.y, 0.f);
            hbB[nc*4+2] = fmaxf(hbB[nc*4+2] + bb.x, 0.f);
            hbB[nc*4+3] = fmaxf(hbB[nc*4+3] + bb.y, 0.f);
        }

        // ---- z = y + h@W2 + b2 ----
        uint32_t hahA[16], halA[16], hahB[16], halB[16];
        c2a<4>(hbA, hahA, halA);
        c2a<4>(hbB, hahB, halB);
        float zvA[16], zvB[16];
#pragma unroll
        for (int i2 = 0; i2 < 16; i2++) { zvA[i2] = 0.f; zvB[i2] = 0.f; }
        gemm2w<4,4,72>(zvA, zvB, hahA, halA, hahB, halB, sm16 + W2H, g, t);

        float2 *opA = (float2*)(out + b0 * 512);
#pragma unroll
        for (int nc = 0; nc < 4; nc++) {
            float2 bb = *(const float2*)(smf + 192 + 8*nc + 2*t);
            opA[g*16 + nc*4 + t]     = make_float2(zvA[nc*4+0] + yvA[nc*4+0] + bb.x,
                                                   zvA[nc*4+1] + yvA[nc*4+1] + bb.y);
            opA[(g+8)*16 + nc*4 + t] = make_float2(zvA[nc*4+2] + yvA[nc*4+2] + bb.x,
                                                   zvA[nc*4+3] + yvA[nc*4+3] + bb.y);
        }
        if (v1) {
            float2 *opB = (float2*)(out + b1s * 512);
#pragma unroll
            for (int nc = 0; nc < 4; nc++) {
                float2 bb = *(const float2*)(smf + 192 + 8*nc + 2*t);
                opB[g*16 + nc*4 + t]     = make_float2(zvB[nc*4+0] + yvB[nc*4+0] + bb.x,
                                                       zvB[nc*4+1] + yvB[nc*4+1] + bb.y);
                opB[(g+8)*16 + nc*4 + t] = make_float2(zvB[nc*4+2] + yvB[nc*4+2] + bb.x,
                                                       zvB[nc*4+3] + yvB[nc*4+3] + bb.y);
            }
        }
        __syncwarp();   // staging reuse barrier for next pair
    }
}

extern "C" void kernel_launch(void* const* d_in, const int* in_sizes, int n_in,
                              void* d_out, int out_size)
{
    const float* x  = (const float*)d_in[0];
    const float* Wq = (const float*)d_in[1];
    const float* bq = (const float*)d_in[2];
    const float* Wk = (const float*)d_in[3];
    const float* bk = (const float*)d_in[4];
    const float* Wv = (const float*)d_in[5];
    const float* bv = (const float*)d_in[6];
    const float* Wo = (const float*)d_in[7];
    const float* bo = (const float*)d_in[8];
    const float* W1 = (const float*)d_in[9];
    const float* b1 = (const float*)d_in[10];
    const float* W2 = (const float*)d_in[11];
    const float* b2 = (const float*)d_in[12];
    float* out = (float*)d_out;

    const int B = in_sizes[0] / 512;                                    // 65536
    const int blocks = (B + BATCHES_PER_BLOCK - 1) / BATCHES_PER_BLOCK; // 2048

    cudaFuncSetAttribute(tinyformer_tc_kernel,
                         cudaFuncAttributeMaxDynamicSharedMemorySize, SMEM_BYTES);
    tinyformer_tc_kernel<<<blocks, THREADS, SMEM_BYTES>>>(x, Wq, bq, Wk, bk, Wv, bv,
                                                          Wo, bo, W1, b1, W2, b2, out, B);
}

// round 12
// speedup vs baseline: 1.5875x; 1.1486x over previous
#include <cuda_runtime.h>
#include <cuda_fp16.h>
#include <cstdint>

// ---------------------------------------------------------------------------
// TinyFormerEncoder R11: 1-term fp16 weight GEMMs (A-hi x B-hi, single mma).
// Error budget: R10 measured 7.7e-5 with exact-A; adding A rounding ~doubles
// it (~1.5e-4), still >5x under the 1e-3 tolerance. Attention (S = QK^T,
// ctx = PV) stays 3-term with split K/V staging to keep softmax logits
// near-exact. Batch pairing + 12 warps/SM kept. mma/batch: 152 -> 88;
// hi-only conversions delete the lo-fragment register arrays.
// ---------------------------------------------------------------------------

namespace {
constexpr int THREADS = 128;          // 4 warps
constexpr int NB = 8;                 // batches per warp (4 pairs)
constexpr int BATCHES_PER_BLOCK = 4 * NB;  // 32

// ushort (fp16) offsets in dynamic smem — hi weight planes only
constexpr int WQH = 0;                     // 32 x stride36
constexpr int WKH = 1152;
constexpr int WVH = 2304;
constexpr int WOH = 3456;
constexpr int W1H = 4608;                  // 64 x stride36
constexpr int W2H = 6912;                  // 32 x stride72
constexpr int BIASU  = 9216;               // 224 floats = 448 ushorts
constexpr int STAGEU = 9664;               // per-warp staging base
constexpr int KS = 34;                     // K row stride (ushorts)
constexpr int VS = 20;                     // vT row stride (ushorts)
constexpr int KH = 0, KL = 16 * KS;        // 0, 544
constexpr int VTH = 2 * 16 * KS;           // 1088
constexpr int VTL = VTH + 32 * VS;         // 1728
constexpr int BATCH_STAGE = VTL + 32 * VS; // 2368
constexpr int WARP_STAGE  = 2 * BATCH_STAGE;
constexpr int SMEM_BYTES = (STAGEU + 4 * WARP_STAGE) * 2;  // 57216
constexpr float SCALE = 0.17677669529663687f;  // 1/sqrt(32)
}

__device__ __forceinline__ uint32_t packh(float e0, float e1) {
    __half2 h = __float22half2_rn(make_float2(e0, e1));   // e0 -> low half
    return *(uint32_t*)&h;
}
__device__ __forceinline__ float2 unpackh(uint32_t v) {
    __half2 h = *(__half2*)&v;
    return __half22float2(h);
}
// exact fp16 split of a pair (attention staging only)
__device__ __forceinline__ void split2(float e0, float e1, uint32_t &h, uint32_t &l) {
    h = packh(e0, e1);
    float2 b = unpackh(h);
    l = packh(e0 - b.x, e1 - b.y);
}
__device__ __forceinline__ unsigned short f2h(float v) {
    __half h = __float2half_rn(v);
    return *(unsigned short*)&h;
}

__device__ __forceinline__ void mma16816(float &c0, float &c1, float &c2, float &c3,
                                         uint32_t a0, uint32_t a1, uint32_t a2, uint32_t a3,
                                         uint32_t b0, uint32_t b1) {
    asm("mma.sync.aligned.m16n8k16.row.col.f32.f16.f16.f32 "
        "{%0,%1,%2,%3}, {%4,%5,%6,%7}, {%8,%9}, {%0,%1,%2,%3};"
        : "+f"(c0), "+f"(c1), "+f"(c2), "+f"(c3)
        : "r"(a0), "r"(a1), "r"(a2), "r"(a3), "r"(b0), "r"(b1));
}

// 3-term split mma (attention: split A x split B, drop lo*lo)
__device__ __forceinline__ void mma3(float *c, const uint32_t *ah, const uint32_t *al,
                                     uint32_t bh0, uint32_t bh1, uint32_t bl0, uint32_t bl1) {
    mma16816(c[0],c[1],c[2],c[3], ah[0],ah[1],ah[2],ah[3], bh0,bh1);
    mma16816(c[0],c[1],c[2],c[3], ah[0],ah[1],ah[2],ah[3], bl0,bl1);
    mma16816(c[0],c[1],c[2],c[3], al[0],al[1],al[2],al[3], bh0,bh1);
}

// hi-only C->A conversion (weight gemm A operands)
template <int KCH>
__device__ __forceinline__ void c2a_hi(const float *C, uint32_t *ah) {
#pragma unroll
    for (int kc = 0; kc < KCH; kc++) {
        ah[kc*4+0] = packh(C[8*kc+0], C[8*kc+1]);
        ah[kc*4+1] = packh(C[8*kc+2], C[8*kc+3]);
        ah[kc*4+2] = packh(C[8*kc+4], C[8*kc+5]);
        ah[kc*4+3] = packh(C[8*kc+6], C[8*kc+7]);
    }
}
// split C->A conversion (attention Q)
template <int KCH>
__device__ __forceinline__ void c2a(const float *C, uint32_t *ah, uint32_t *al) {
#pragma unroll
    for (int kc = 0; kc < KCH; kc++) {
        split2(C[8*kc+0], C[8*kc+1], ah[kc*4+0], al[kc*4+0]);
        split2(C[8*kc+2], C[8*kc+3], ah[kc*4+1], al[kc*4+1]);
        split2(C[8*kc+4], C[8*kc+5], ah[kc*4+2], al[kc*4+2]);
        split2(C[8*kc+6], C[8*kc+7], ah[kc*4+3], al[kc*4+3]);
    }
}

// 3-term single-batch gemm (attention)
template <int KCH, int NCH, int RS>
__device__ __forceinline__ void gemm(float *C, const uint32_t *ah, const uint32_t *al,
                                     const unsigned short *wh, const unsigned short *wl,
                                     int g, int t) {
#pragma unroll
    for (int j = 0; j < NCH; j++) {
#pragma unroll
        for (int kc = 0; kc < KCH; kc++) {
            const unsigned short *ph = wh + (8*j + g)*RS + kc*16 + 2*t;
            const unsigned short *pl = wl + (8*j + g)*RS + kc*16 + 2*t;
            uint32_t bh0 = *(const uint32_t*)ph, bh1 = *(const uint32_t*)(ph + 8);
            uint32_t bl0 = *(const uint32_t*)pl, bl1 = *(const uint32_t*)(pl + 8);
            mma3(C + j*4, ah + kc*4, al + kc*4, bh0, bh1, bl0, bl1);
        }
    }
}

// 1-term batch-paired weight gemm (A-hi x B-hi)
template <int KCH, int NCH, int RS>
__device__ __forceinline__ void gemm1w(float *CA, float *CB,
                                       const uint32_t *ahA, const uint32_t *ahB,
                                       const unsigned short *wh, int g, int t) {
#pragma unroll
    for (int j = 0; j < NCH; j++) {
#pragma unroll
        for (int kc = 0; kc < KCH; kc++) {
            const unsigned short *ph = wh + (8*j + g)*RS + kc*16 + 2*t;
            uint32_t b0 = *(const uint32_t*)ph, b1 = *(const uint32_t*)(ph + 8);
            mma16816(CA[j*4+0],CA[j*4+1],CA[j*4+2],CA[j*4+3],
                     ahA[kc*4+0],ahA[kc*4+1],ahA[kc*4+2],ahA[kc*4+3], b0,b1);
            mma16816(CB[j*4+0],CB[j*4+1],CB[j*4+2],CB[j*4+3],
                     ahB[kc*4+0],ahB[kc*4+1],ahB[kc*4+2],ahB[kc*4+3], b0,b1);
        }
    }
}

__global__ void __launch_bounds__(THREADS, 3)
tinyformer_tc_kernel(const float *__restrict__ x,
                     const float *__restrict__ Wq, const float *__restrict__ bq,
                     const float *__restrict__ Wk, const float *__restrict__ bk,
                     const float *__restrict__ Wv, const float *__restrict__ bv,
                     const float *__restrict__ Wo, const float *__restrict__ bo,
                     const float *__restrict__ W1, const float *__restrict__ b1,
                     const float *__restrict__ W2, const float *__restrict__ b2,
                     float *__restrict__ out, int B)
{
    extern __shared__ unsigned short sm16[];
    float *smf = (float*)(sm16 + BIASU);
    const int tid = threadIdx.x;

    // ---- stage weights: transpose to fp16 hi planes ----
    for (int i = tid; i < 1024; i += THREADS) {
        int d = i >> 5, j = i & 31;
        int o = j*36 + d;
        sm16[WQH + o] = f2h(Wq[i]);
        sm16[WKH + o] = f2h(Wk[i]);
        sm16[WVH + o] = f2h(Wv[i]);
        sm16[WOH + o] = f2h(Wo[i]);
    }
    for (int i = tid; i < 2048; i += THREADS) {
        {   int d = i >> 6, j = i & 63;
            sm16[W1H + j*36 + d] = f2h(W1[i]); }
        {   int h = i >> 5, j = i & 31;
            sm16[W2H + j*72 + h] = f2h(W2[i]); }
    }
    if (tid < 32) {
        smf[0   + tid] = bq[tid]; smf[32 + tid] = bk[tid]; smf[64 + tid] = bv[tid];
        smf[96  + tid] = bo[tid]; smf[192 + tid] = b2[tid];
    }
    if (tid < 64) smf[128 + tid] = b1[tid];
    __syncthreads();

    const int warp = tid >> 5, lane = tid & 31;
    const int g = lane >> 2, t = lane & 3;
    unsigned short *stgA = sm16 + STAGEU + warp * WARP_STAGE;
    unsigned short *stgB = stgA + BATCH_STAGE;

    for (int it = 0; it < NB/2; it++) {
        size_t b0 = (size_t)blockIdx.x * BATCHES_PER_BLOCK + warp * NB + 2*it;
        if (b0 >= (size_t)B) continue;           // warp-uniform
        size_t b1s = b0 + 1;
        const bool v1 = b1s < (size_t)B;
        if (!v1) b1s = b0;

        // ---- x (both batches) in C-fragment layout, fp32 ----
        const float2 *xpA = (const float2*)(x + b0 * 512);
        const float2 *xpB = (const float2*)(x + b1s * 512);
        float xcA[16], xcB[16];
#pragma unroll
        for (int nc = 0; nc < 4; nc++) {
            float2 p0 = xpA[g*16 + nc*4 + t], p1 = xpA[(g+8)*16 + nc*4 + t];
            xcA[nc*4+0] = p0.x; xcA[nc*4+1] = p0.y;
            xcA[nc*4+2] = p1.x; xcA[nc*4+3] = p1.y;
            float2 q0 = xpB[g*16 + nc*4 + t], q1 = xpB[(g+8)*16 + nc*4 + t];
            xcB[nc*4+0] = q0.x; xcB[nc*4+1] = q0.y;
            xcB[nc*4+2] = q1.x; xcB[nc*4+3] = q1.y;
        }
        uint32_t xahA[8], xahB[8];
        c2a_hi<2>(xcA, xahA);
        c2a_hi<2>(xcB, xahB);

        float CA[16], CB[16];

        // ---- K (both) -> SPLIT-stored row-major (attention is 3-term) ----
#pragma unroll
        for (int i2 = 0; i2 < 16; i2++) { CA[i2] = 0.f; CB[i2] = 0.f; }
        gemm1w<2,4,36>(CA, CB, xahA, xahB, sm16 + WKH, g, t);
#pragma unroll
        for (int nc = 0; nc < 4; nc++) {
            float2 bb = *(const float2*)(smf + 32 + 8*nc + 2*t);
            int c0 = nc*8 + 2*t;
            uint32_t h0, l0, h1, l1;
            split2(CA[nc*4+0] + bb.x, CA[nc*4+1] + bb.y, h0, l0);
            split2(CA[nc*4+2] + bb.x, CA[nc*4+3] + bb.y, h1, l1);
            *(uint32_t*)(stgA + KH + g*KS     + c0) = h0;
            *(uint32_t*)(stgA + KL + g*KS     + c0) = l0;
            *(uint32_t*)(stgA + KH + (g+8)*KS + c0) = h1;
            *(uint32_t*)(stgA + KL + (g+8)*KS + c0) = l1;
            split2(CB[nc*4+0] + bb.x, CB[nc*4+1] + bb.y, h0, l0);
            split2(CB[nc*4+2] + bb.x, CB[nc*4+3] + bb.y, h1, l1);
            *(uint32_t*)(stgB + KH + g*KS     + c0) = h0;
            *(uint32_t*)(stgB + KL + g*KS     + c0) = l0;
            *(uint32_t*)(stgB + KH + (g+8)*KS + c0) = h1;
            *(uint32_t*)(stgB + KL + (g+8)*KS + c0) = l1;
        }

        // ---- V (both) -> SPLIT-stored TRANSPOSED ----
#pragma unroll
        for (int i2 = 0; i2 < 16; i2++) { CA[i2] = 0.f; CB[i2] = 0.f; }
        gemm1w<2,4,36>(CA, CB, xahA, xahB, sm16 + WVH, g, t);
#pragma unroll
        for (int nc = 0; nc < 4; nc++) {
            float2 bb = *(const float2*)(smf + 64 + 8*nc + 2*t);
            int col0 = 8*nc + 2*t;
#pragma unroll
            for (int m = 0; m < 4; m++) {
                int col = col0 + (m & 1);
                int row = (m < 2) ? g : g + 8;
                float eA = CA[nc*4+m] + ((m & 1) ? bb.y : bb.x);
                unsigned short hA = f2h(eA);
                __half hv = *(__half*)&hA;
                stgA[VTH + col*VS + row] = hA;
                stgA[VTL + col*VS + row] = f2h(eA - __half2float(hv));
                float eB = CB[nc*4+m] + ((m & 1) ? bb.y : bb.x);
                unsigned short hB = f2h(eB);
                __half hv2 = *(__half*)&hB;
                stgB[VTH + col*VS + row] = hB;
                stgB[VTL + col*VS + row] = f2h(eB - __half2float(hv2));
            }
        }

        // ---- Q (both) -> scaled split A-fragments (attention needs split) ----
#pragma unroll
        for (int i2 = 0; i2 < 16; i2++) { CA[i2] = 0.f; CB[i2] = 0.f; }
        gemm1w<2,4,36>(CA, CB, xahA, xahB, sm16 + WQH, g, t);
        uint32_t qahA[8], qalA[8], qahB[8], qalB[8];
        {
            float qc[16];
#pragma unroll
            for (int nc = 0; nc < 4; nc++) {
                float2 bb = *(const float2*)(smf + 0 + 8*nc + 2*t);
                qc[nc*4+0] = (CA[nc*4+0] + bb.x) * SCALE;
                qc[nc*4+1] = (CA[nc*4+1] + bb.y) * SCALE;
                qc[nc*4+2] = (CA[nc*4+2] + bb.x) * SCALE;
                qc[nc*4+3] = (CA[nc*4+3] + bb.y) * SCALE;
            }
            c2a<2>(qc, qahA, qalA);
#pragma unroll
            for (int nc = 0; nc < 4; nc++) {
                float2 bb = *(const float2*)(smf + 0 + 8*nc + 2*t);
                qc[nc*4+0] = (CB[nc*4+0] + bb.x) * SCALE;
                qc[nc*4+1] = (CB[nc*4+1] + bb.y) * SCALE;
                qc[nc*4+2] = (CB[nc*4+2] + bb.x) * SCALE;
                qc[nc*4+3] = (CB[nc*4+3] + bb.y) * SCALE;
            }
            c2a<2>(qc, qahB, qalB);
        }
        __syncwarp();

        // ---- S = Q@K^T (3-term), softmax, P frags (per batch) ----
        uint32_t pahA[4], palA[4], pahB[4], palB[4];
#pragma unroll
        for (int side = 0; side < 2; side++) {
            const unsigned short *kh = (side ? stgB : stgA) + KH;
            const unsigned short *kl = (side ? stgB : stgA) + KL;
            float s[8];
#pragma unroll
            for (int i2 = 0; i2 < 8; i2++) s[i2] = 0.f;
            if (side) gemm<2,2,KS>(s, qahB, qalB, kh, kl, g, t);
            else      gemm<2,2,KS>(s, qahA, qalA, kh, kl, g, t);

            float m0 = fmaxf(fmaxf(s[0], s[1]), fmaxf(s[4], s[5]));
            float m1 = fmaxf(fmaxf(s[2], s[3]), fmaxf(s[6], s[7]));
            m0 = fmaxf(m0, __shfl_xor_sync(0xffffffffu, m0, 1));
            m0 = fmaxf(m0, __shfl_xor_sync(0xffffffffu, m0, 2));
            m1 = fmaxf(m1, __shfl_xor_sync(0xffffffffu, m1, 1));
            m1 = fmaxf(m1, __shfl_xor_sync(0xffffffffu, m1, 2));
            s[0] = __expf(s[0] - m0); s[1] = __expf(s[1] - m0);
            s[4] = __expf(s[4] - m0); s[5] = __expf(s[5] - m0);
            s[2] = __expf(s[2] - m1); s[3] = __expf(s[3] - m1);
            s[6] = __expf(s[6] - m1); s[7] = __expf(s[7] - m1);
            float t0 = s[0] + s[1] + s[4] + s[5];
            float t1 = s[2] + s[3] + s[6] + s[7];
            t0 += __shfl_xor_sync(0xffffffffu, t0, 1);
            t0 += __shfl_xor_sync(0xffffffffu, t0, 2);
            t1 += __shfl_xor_sync(0xffffffffu, t1, 1);
            t1 += __shfl_xor_sync(0xffffffffu, t1, 2);
            float i0 = 1.f / t0, i1 = 1.f / t1;
            s[0] *= i0; s[1] *= i0; s[4] *= i0; s[5] *= i0;
            s[2] *= i1; s[3] *= i1; s[6] *= i1; s[7] *= i1;

            uint32_t *ph = side ? pahB : pahA;
            uint32_t *pl = side ? palB : palA;
            split2(s[0], s[1], ph[0], pl[0]);
            split2(s[2], s[3], ph[1], pl[1]);
            split2(s[4], s[5], ph[2], pl[2]);
            split2(s[6], s[7], ph[3], pl[3]);
        }

        // ---- ctx = P@V (3-term, per batch) ----
#pragma unroll
        for (int i2 = 0; i2 < 16; i2++) { CA[i2] = 0.f; CB[i2] = 0.f; }
        gemm<1,4,VS>(CA, pahA, palA, stgA + VTH, stgA + VTL, g, t);
        gemm<1,4,VS>(CB, pahB, palB, stgB + VTH, stgB + VTL, g, t);

        // ---- y = x + ctx@Wo + bo ----
        uint32_t cahA[8], cahB[8];
        c2a_hi<2>(CA, cahA);
        c2a_hi<2>(CB, cahB);
        float yvA[16], yvB[16];
#pragma unroll
        for (int i2 = 0; i2 < 16; i2++) { yvA[i2] = 0.f; yvB[i2] = 0.f; }
        gemm1w<2,4,36>(yvA, yvB, cahA, cahB, sm16 + WOH, g, t);
#pragma unroll
        for (int nc = 0; nc < 4; nc++) {
            float2 bb = *(const float2*)(smf + 96 + 8*nc + 2*t);
            yvA[nc*4+0] += xcA[nc*4+0] + bb.x;
            yvA[nc*4+1] += xcA[nc*4+1] + bb.y;
            yvA[nc*4+2] += xcA[nc*4+2] + bb.x;
            yvA[nc*4+3] += xcA[nc*4+3] + bb.y;
            yvB[nc*4+0] += xcB[nc*4+0] + bb.x;
            yvB[nc*4+1] += xcB[nc*4+1] + bb.y;
            yvB[nc*4+2] += xcB[nc*4+2] + bb.x;
            yvB[nc*4+3] += xcB[nc*4+3] + bb.y;
        }

        // ---- h = relu(y@W1 + b1) ----
        uint32_t yahA[8], yahB[8];
        c2a_hi<2>(yvA, yahA);
        c2a_hi<2>(yvB, yahB);
        float hbA[32], hbB[32];
#pragma unroll
        for (int i2 = 0; i2 < 32; i2++) { hbA[i2] = 0.f; hbB[i2] = 0.f; }
        gemm1w<2,8,36>(hbA, hbB, yahA, yahB, sm16 + W1H, g, t);
#pragma unroll
        for (int nc = 0; nc < 8; nc++) {
            float2 bb = *(const float2*)(smf + 128 + 8*nc + 2*t);
            hbA[nc*4+0] = fmaxf(hbA[nc*4+0] + bb.x, 0.f);
            hbA[nc*4+1] = fmaxf(hbA[nc*4+1] + bb.y, 0.f);
            hbA[nc*4+2] = fmaxf(hbA[nc*4+2] + bb.x, 0.f);
            hbA[nc*4+3] = fmaxf(hbA[nc*4+3] + bb.y, 0.f);
            hbB[nc*4+0] = fmaxf(hbB[nc*4+0] + bb.x, 0.f);
            hbB[nc*4+1] = fmaxf(hbB[nc*4+1] + bb.y, 0.f);
            hbB[nc*4+2] = fmaxf(hbB[nc*4+2] + bb.x, 0.f);
            hbB[nc*4+3] = fmaxf(hbB[nc*4+3] + bb.y, 0.f);
        }

        // ---- z = y + h@W2 + b2 ----
        uint32_t hahA[16], hahB[16];
        c2a_hi<4>(hbA, hahA);
        c2a_hi<4>(hbB, hahB);
        float zvA[16], zvB[16];
#pragma unroll
        for (int i2 = 0; i2 < 16; i2++) { zvA[i2] = 0.f; zvB[i2] = 0.f; }
        gemm1w<4,4,72>(zvA, zvB, hahA, hahB, sm16 + W2H, g, t);

        float2 *opA = (float2*)(out + b0 * 512);
#pragma unroll
        for (int nc = 0; nc < 4; nc++) {
            float2 bb = *(const float2*)(smf + 192 + 8*nc + 2*t);
            opA[g*16 + nc*4 + t]     = make_float2(zvA[nc*4+0] + yvA[nc*4+0] + bb.x,
                                                   zvA[nc*4+1] + yvA[nc*4+1] + bb.y);
            opA[(g+8)*16 + nc*4 + t] = make_float2(zvA[nc*4+2] + yvA[nc*4+2] + bb.x,
                                                   zvA[nc*4+3] + yvA[nc*4+3] + bb.y);
        }
        if (v1) {
            float2 *opB = (float2*)(out + b1s * 512);
#pragma unroll
            for (int nc = 0; nc < 4; nc++) {
                float2 bb = *(const float2*)(smf + 192 + 8*nc + 2*t);
                opB[g*16 + nc*4 + t]     = make_float2(zvB[nc*4+0] + yvB[nc*4+0] + bb.x,
                                                       zvB[nc*4+1] + yvB[nc*4+1] + bb.y);
                opB[(g+8)*16 + nc*4 + t] = make_float2(zvB[nc*4+2] + yvB[nc*4+2] + bb.x,
                                                       zvB[nc*4+3] + yvB[nc*4+3] + bb.y);
            }
        }
        __syncwarp();   // staging reuse barrier for next pair
    }
}

extern "C" void kernel_launch(void* const* d_in, const int* in_sizes, int n_in,
                              void* d_out, int out_size)
{
    const float* x  = (const float*)d_in[0];
    const float* Wq = (const float*)d_in[1];
    const float* bq = (const float*)d_in[2];
    const float* Wk = (const float*)d_in[3];
    const float* bk = (const float*)d_in[4];
    const float* Wv = (const float*)d_in[5];
    const float* bv = (const float*)d_in[6];
    const float* Wo = (const float*)d_in[7];
    const float* bo = (const float*)d_in[8];
    const float* W1 = (const float*)d_in[9];
    const float* b1 = (const float*)d_in[10];
    const float* W2 = (const float*)d_in[11];
    const float* b2 = (const float*)d_in[12];
    float* out = (float*)d_out;

    const int B = in_sizes[0] / 512;                                    // 65536
    const int blocks = (B + BATCHES_PER_BLOCK - 1) / BATCHES_PER_BLOCK; // 2048

    cudaFuncSetAttribute(tinyformer_tc_kernel,
                         cudaFuncAttributeMaxDynamicSharedMemorySize, SMEM_BYTES);
    tinyformer_tc_kernel<<<blocks, THREADS, SMEM_BYTES>>>(x, Wq, bq, Wk, bk, Wv, bv,
                                                          Wo, bo, W1, b1, W2, b2, out, B);
}

// round 13
// speedup vs baseline: 1.9657x; 1.2382x over previous
#include <cuda_runtime.h>
#include <cuda_fp16.h>
#include <cstdint>

// ---------------------------------------------------------------------------
// TinyFormerEncoder R12:
//  - conflict-free smem strides (weights 40, K 40, vT 24): halves LDS wavefronts
//  - 2-term attention: K/V staged hi-only (Q/P exact-split), mma/batch 88->72
//  - FFN split into two halves to halve h-register live range
//  - 43.4KB smem/block -> 4 blocks/SM (16 warps) with __launch_bounds__(128,4)
// ---------------------------------------------------------------------------

namespace {
constexpr int THREADS = 128;          // 4 warps
constexpr int NB = 8;                 // batches per warp (4 pairs)
constexpr int BATCHES_PER_BLOCK = 4 * NB;  // 32

// ushort (fp16) offsets in dynamic smem — hi weight planes, stride 40
constexpr int WQH = 0;                     // 32 x 40
constexpr int WKH = 1280;
constexpr int WVH = 2560;
constexpr int WOH = 3840;
constexpr int W1H = 5120;                  // 64 x 40
constexpr int W2H = 7680;                  // 32 x 72
constexpr int BIASU  = 9984;               // 224 floats = 448 ushorts
constexpr int STAGEU = 10432;              // per-warp staging base
constexpr int KS = 40;                     // K row stride (ushorts) — conflict-free
constexpr int VS = 24;                     // vT row stride — conflict-free
constexpr int KH = 0;                      // K hi plane: 16 x KS = 640
constexpr int VTH = 640;                   // vT hi plane: 32 x VS = 768
constexpr int BATCH_STAGE = VTH + 32 * VS; // 1408
constexpr int WARP_STAGE  = 2 * BATCH_STAGE;
constexpr int SMEM_BYTES = (STAGEU + 4 * WARP_STAGE) * 2;  // 43392
constexpr float SCALE = 0.17677669529663687f;  // 1/sqrt(32)
}

__device__ __forceinline__ uint32_t packh(float e0, float e1) {
    __half2 h = __float22half2_rn(make_float2(e0, e1));   // e0 -> low half
    return *(uint32_t*)&h;
}
__device__ __forceinline__ float2 unpackh(uint32_t v) {
    __half2 h = *(__half2*)&v;
    return __half22float2(h);
}
// exact fp16 split of a pair (Q / P fragments)
__device__ __forceinline__ void split2(float e0, float e1, uint32_t &h, uint32_t &l) {
    h = packh(e0, e1);
    float2 b = unpackh(h);
    l = packh(e0 - b.x, e1 - b.y);
}
__device__ __forceinline__ unsigned short f2h(float v) {
    __half h = __float2half_rn(v);
    return *(unsigned short*)&h;
}

__device__ __forceinline__ void mma16816(float &c0, float &c1, float &c2, float &c3,
                                         uint32_t a0, uint32_t a1, uint32_t a2, uint32_t a3,
                                         uint32_t b0, uint32_t b1) {
    asm("mma.sync.aligned.m16n8k16.row.col.f32.f16.f16.f32 "
        "{%0,%1,%2,%3}, {%4,%5,%6,%7}, {%8,%9}, {%0,%1,%2,%3};"
        : "+f"(c0), "+f"(c1), "+f"(c2), "+f"(c3)
        : "r"(a0), "r"(a1), "r"(a2), "r"(a3), "r"(b0), "r"(b1));
}

// hi-only C->A conversion
template <int KCH>
__device__ __forceinline__ void c2a_hi(const float *C, uint32_t *ah) {
#pragma unroll
    for (int kc = 0; kc < KCH; kc++) {
        ah[kc*4+0] = packh(C[8*kc+0], C[8*kc+1]);
        ah[kc*4+1] = packh(C[8*kc+2], C[8*kc+3]);
        ah[kc*4+2] = packh(C[8*kc+4], C[8*kc+5]);
        ah[kc*4+3] = packh(C[8*kc+6], C[8*kc+7]);
    }
}
// split C->A conversion (Q)
template <int KCH>
__device__ __forceinline__ void c2a(const float *C, uint32_t *ah, uint32_t *al) {
#pragma unroll
    for (int kc = 0; kc < KCH; kc++) {
        split2(C[8*kc+0], C[8*kc+1], ah[kc*4+0], al[kc*4+0]);
        split2(C[8*kc+2], C[8*kc+3], ah[kc*4+1], al[kc*4+1]);
        split2(C[8*kc+4], C[8*kc+5], ah[kc*4+2], al[kc*4+2]);
        split2(C[8*kc+6], C[8*kc+7], ah[kc*4+3], al[kc*4+3]);
    }
}

// 1-term batch-paired weight gemm (A-hi x B-hi)
template <int KCH, int NCH, int RS>
__device__ __forceinline__ void gemm1w(float *CA, float *CB,
                                       const uint32_t *ahA, const uint32_t *ahB,
                                       const unsigned short *wh, int g, int t) {
#pragma unroll
    for (int j = 0; j < NCH; j++) {
#pragma unroll
        for (int kc = 0; kc < KCH; kc++) {
            const unsigned short *ph = wh + (8*j + g)*RS + kc*16 + 2*t;
            uint32_t b0 = *(const uint32_t*)ph, b1 = *(const uint32_t*)(ph + 8);
            mma16816(CA[j*4+0],CA[j*4+1],CA[j*4+2],CA[j*4+3],
                     ahA[kc*4+0],ahA[kc*4+1],ahA[kc*4+2],ahA[kc*4+3], b0,b1);
            mma16816(CB[j*4+0],CB[j*4+1],CB[j*4+2],CB[j*4+3],
                     ahB[kc*4+0],ahB[kc*4+1],ahB[kc*4+2],ahB[kc*4+3], b0,b1);
        }
    }
}

// 2-term split-A gemm (attention: exact-split A x hi-only B)
template <int KCH, int NCH, int RS>
__device__ __forceinline__ void gemm_a2(float *C, const uint32_t *ah, const uint32_t *al,
                                        const unsigned short *wh, int g, int t) {
#pragma unroll
    for (int j = 0; j < NCH; j++) {
#pragma unroll
        for (int kc = 0; kc < KCH; kc++) {
            const unsigned short *ph = wh + (8*j + g)*RS + kc*16 + 2*t;
            uint32_t b0 = *(const uint32_t*)ph, b1 = *(const uint32_t*)(ph + 8);
            mma16816(C[j*4+0],C[j*4+1],C[j*4+2],C[j*4+3],
                     ah[kc*4+0],ah[kc*4+1],ah[kc*4+2],ah[kc*4+3], b0,b1);
            mma16816(C[j*4+0],C[j*4+1],C[j*4+2],C[j*4+3],
                     al[kc*4+0],al[kc*4+1],al[kc*4+2],al[kc*4+3], b0,b1);
        }
    }
}

__global__ void __launch_bounds__(THREADS, 4)
tinyformer_tc_kernel(const float *__restrict__ x,
                     const float *__restrict__ Wq, const float *__restrict__ bq,
                     const float *__restrict__ Wk, const float *__restrict__ bk,
                     const float *__restrict__ Wv, const float *__restrict__ bv,
                     const float *__restrict__ Wo, const float *__restrict__ bo,
                     const float *__restrict__ W1, const float *__restrict__ b1,
                     const float *__restrict__ W2, const float *__restrict__ b2,
                     float *__restrict__ out, int B)
{
    extern __shared__ unsigned short sm16[];
    float *smf = (float*)(sm16 + BIASU);
    const int tid = threadIdx.x;

    // ---- stage weights: transpose to fp16 hi planes (stride 40 / 72) ----
    for (int i = tid; i < 1024; i += THREADS) {
        int d = i >> 5, j = i & 31;
        int o = j*40 + d;
        sm16[WQH + o] = f2h(Wq[i]);
        sm16[WKH + o] = f2h(Wk[i]);
        sm16[WVH + o] = f2h(Wv[i]);
        sm16[WOH + o] = f2h(Wo[i]);
    }
    for (int i = tid; i < 2048; i += THREADS) {
        {   int d = i >> 6, j = i & 63;
            sm16[W1H + j*40 + d] = f2h(W1[i]); }
        {   int h = i >> 5, j = i & 31;
            sm16[W2H + j*72 + h] = f2h(W2[i]); }
    }
    if (tid < 32) {
        smf[0   + tid] = bq[tid]; smf[32 + tid] = bk[tid]; smf[64 + tid] = bv[tid];
        smf[96  + tid] = bo[tid]; smf[192 + tid] = b2[tid];
    }
    if (tid < 64) smf[128 + tid] = b1[tid];
    __syncthreads();

    const int warp = tid >> 5, lane = tid & 31;
    const int g = lane >> 2, t = lane & 3;
    unsigned short *stgA = sm16 + STAGEU + warp * WARP_STAGE;
    unsigned short *stgB = stgA + BATCH_STAGE;

    for (int it = 0; it < NB/2; it++) {
        size_t b0 = (size_t)blockIdx.x * BATCHES_PER_BLOCK + warp * NB + 2*it;
        if (b0 >= (size_t)B) continue;           // warp-uniform
        size_t b1s = b0 + 1;
        const bool v1 = b1s < (size_t)B;
        if (!v1) b1s = b0;

        // ---- x (both batches) in C-fragment layout, fp32 ----
        const float2 *xpA = (const float2*)(x + b0 * 512);
        const float2 *xpB = (const float2*)(x + b1s * 512);
        float xcA[16], xcB[16];
#pragma unroll
        for (int nc = 0; nc < 4; nc++) {
            float2 p0 = xpA[g*16 + nc*4 + t], p1 = xpA[(g+8)*16 + nc*4 + t];
            xcA[nc*4+0] = p0.x; xcA[nc*4+1] = p0.y;
            xcA[nc*4+2] = p1.x; xcA[nc*4+3] = p1.y;
            float2 q0 = xpB[g*16 + nc*4 + t], q1 = xpB[(g+8)*16 + nc*4 + t];
            xcB[nc*4+0] = q0.x; xcB[nc*4+1] = q0.y;
            xcB[nc*4+2] = q1.x; xcB[nc*4+3] = q1.y;
        }
        uint32_t xahA[8], xahB[8];
        c2a_hi<2>(xcA, xahA);
        c2a_hi<2>(xcB, xahB);

        float CA[16], CB[16];

        // ---- K (both) -> hi-only row-major staging ----
#pragma unroll
        for (int i2 = 0; i2 < 16; i2++) { CA[i2] = 0.f; CB[i2] = 0.f; }
        gemm1w<2,4,40>(CA, CB, xahA, xahB, sm16 + WKH, g, t);
#pragma unroll
        for (int nc = 0; nc < 4; nc++) {
            float2 bb = *(const float2*)(smf + 32 + 8*nc + 2*t);
            int c0 = nc*8 + 2*t;
            *(uint32_t*)(stgA + KH + g*KS     + c0) = packh(CA[nc*4+0] + bb.x, CA[nc*4+1] + bb.y);
            *(uint32_t*)(stgA + KH + (g+8)*KS + c0) = packh(CA[nc*4+2] + bb.x, CA[nc*4+3] + bb.y);
            *(uint32_t*)(stgB + KH + g*KS     + c0) = packh(CB[nc*4+0] + bb.x, CB[nc*4+1] + bb.y);
            *(uint32_t*)(stgB + KH + (g+8)*KS + c0) = packh(CB[nc*4+2] + bb.x, CB[nc*4+3] + bb.y);
        }

        // ---- V (both) -> hi-only TRANSPOSED staging ----
#pragma unroll
        for (int i2 = 0; i2 < 16; i2++) { CA[i2] = 0.f; CB[i2] = 0.f; }
        gemm1w<2,4,40>(CA, CB, xahA, xahB, sm16 + WVH, g, t);
#pragma unroll
        for (int nc = 0; nc < 4; nc++) {
            float2 bb = *(const float2*)(smf + 64 + 8*nc + 2*t);
            int col0 = 8*nc + 2*t;
#pragma unroll
            for (int m = 0; m < 4; m++) {
                int col = col0 + (m & 1);
                int row = (m < 2) ? g : g + 8;
                stgA[VTH + col*VS + row] = f2h(CA[nc*4+m] + ((m & 1) ? bb.y : bb.x));
                stgB[VTH + col*VS + row] = f2h(CB[nc*4+m] + ((m & 1) ? bb.y : bb.x));
            }
        }

        // ---- Q (both) -> scaled split A-fragments ----
#pragma unroll
        for (int i2 = 0; i2 < 16; i2++) { CA[i2] = 0.f; CB[i2] = 0.f; }
        gemm1w<2,4,40>(CA, CB, xahA, xahB, sm16 + WQH, g, t);
        uint32_t qahA[8], qalA[8], qahB[8], qalB[8];
        {
            float qc[16];
#pragma unroll
            for (int nc = 0; nc < 4; nc++) {
                float2 bb = *(const float2*)(smf + 0 + 8*nc + 2*t);
                qc[nc*4+0] = (CA[nc*4+0] + bb.x) * SCALE;
                qc[nc*4+1] = (CA[nc*4+1] + bb.y) * SCALE;
                qc[nc*4+2] = (CA[nc*4+2] + bb.x) * SCALE;
                qc[nc*4+3] = (CA[nc*4+3] + bb.y) * SCALE;
            }
            c2a<2>(qc, qahA, qalA);
#pragma unroll
            for (int nc = 0; nc < 4; nc++) {
                float2 bb = *(const float2*)(smf + 0 + 8*nc + 2*t);
                qc[nc*4+0] = (CB[nc*4+0] + bb.x) * SCALE;
                qc[nc*4+1] = (CB[nc*4+1] + bb.y) * SCALE;
                qc[nc*4+2] = (CB[nc*4+2] + bb.x) * SCALE;
                qc[nc*4+3] = (CB[nc*4+3] + bb.y) * SCALE;
            }
            c2a<2>(qc, qahB, qalB);
        }
        __syncwarp();

        // ---- S = Q@K^T (2-term), softmax, P frags (per batch) ----
        uint32_t pahA[4], palA[4], pahB[4], palB[4];
#pragma unroll
        for (int side = 0; side < 2; side++) {
            const unsigned short *kh = (side ? stgB : stgA) + KH;
            float s[8];
#pragma unroll
            for (int i2 = 0; i2 < 8; i2++) s[i2] = 0.f;
            if (side) gemm_a2<2,2,KS>(s, qahB, qalB, kh, g, t);
            else      gemm_a2<2,2,KS>(s, qahA, qalA, kh, g, t);

            float m0 = fmaxf(fmaxf(s[0], s[1]), fmaxf(s[4], s[5]));
            float m1 = fmaxf(fmaxf(s[2], s[3]), fmaxf(s[6], s[7]));
            m0 = fmaxf(m0, __shfl_xor_sync(0xffffffffu, m0, 1));
            m0 = fmaxf(m0, __shfl_xor_sync(0xffffffffu, m0, 2));
            m1 = fmaxf(m1, __shfl_xor_sync(0xffffffffu, m1, 1));
            m1 = fmaxf(m1, __shfl_xor_sync(0xffffffffu, m1, 2));
            s[0] = __expf(s[0] - m0); s[1] = __expf(s[1] - m0);
            s[4] = __expf(s[4] - m0); s[5] = __expf(s[5] - m0);
            s[2] = __expf(s[2] - m1); s[3] = __expf(s[3] - m1);
            s[6] = __expf(s[6] - m1); s[7] = __expf(s[7] - m1);
            float t0 = s[0] + s[1] + s[4] + s[5];
            float t1 = s[2] + s[3] + s[6] + s[7];
            t0 += __shfl_xor_sync(0xffffffffu, t0, 1);
            t0 += __shfl_xor_sync(0xffffffffu, t0, 2);
            t1 += __shfl_xor_sync(0xffffffffu, t1, 1);
            t1 += __shfl_xor_sync(0xffffffffu, t1, 2);
            float i0 = 1.f / t0, i1 = 1.f / t1;
            s[0] *= i0; s[1] *= i0; s[4] *= i0; s[5] *= i0;
            s[2] *= i1; s[3] *= i1; s[6] *= i1; s[7] *= i1;

            uint32_t *ph = side ? pahB : pahA;
            uint32_t *pl = side ? palB : palA;
            split2(s[0], s[1], ph[0], pl[0]);
            split2(s[2], s[3], ph[1], pl[1]);
            split2(s[4], s[5], ph[2], pl[2]);
            split2(s[6], s[7], ph[3], pl[3]);
        }

        // ---- ctx = P@V (2-term, per batch) ----
#pragma unroll
        for (int i2 = 0; i2 < 16; i2++) { CA[i2] = 0.f; CB[i2] = 0.f; }
        gemm_a2<1,4,VS>(CA, pahA, palA, stgA + VTH, g, t);
        gemm_a2<1,4,VS>(CB, pahB, palB, stgB + VTH, g, t);

        // ---- y = x + ctx@Wo + bo ----
        uint32_t cahA[8], cahB[8];
        c2a_hi<2>(CA, cahA);
        c2a_hi<2>(CB, cahB);
        float yvA[16], yvB[16];
#pragma unroll
        for (int i2 = 0; i2 < 16; i2++) { yvA[i2] = 0.f; yvB[i2] = 0.f; }
        gemm1w<2,4,40>(yvA, yvB, cahA, cahB, sm16 + WOH, g, t);
#pragma unroll
        for (int nc = 0; nc < 4; nc++) {
            float2 bb = *(const float2*)(smf + 96 + 8*nc + 2*t);
            yvA[nc*4+0] += xcA[nc*4+0] + bb.x;
            yvA[nc*4+1] += xcA[nc*4+1] + bb.y;
            yvA[nc*4+2] += xcA[nc*4+2] + bb.x;
            yvA[nc*4+3] += xcA[nc*4+3] + bb.y;
            yvB[nc*4+0] += xcB[nc*4+0] + bb.x;
            yvB[nc*4+1] += xcB[nc*4+1] + bb.y;
            yvB[nc*4+2] += xcB[nc*4+2] + bb.x;
            yvB[nc*4+3] += xcB[nc*4+3] + bb.y;
        }

        // ---- FFN in two halves (halves h live registers) ----
        uint32_t yahA[8], yahB[8];
        c2a_hi<2>(yvA, yahA);
        c2a_hi<2>(yvB, yahB);
        float zvA[16], zvB[16];
#pragma unroll
        for (int i2 = 0; i2 < 16; i2++) { zvA[i2] = 0.f; zvB[i2] = 0.f; }
#pragma unroll
        for (int fh = 0; fh < 2; fh++) {
            float hbA[16], hbB[16];
#pragma unroll
            for (int i2 = 0; i2 < 16; i2++) { hbA[i2] = 0.f; hbB[i2] = 0.f; }
            gemm1w<2,4,40>(hbA, hbB, yahA, yahB, sm16 + W1H + fh*32*40, g, t);
#pragma unroll
            for (int nc = 0; nc < 4; nc++) {
                float2 bb = *(const float2*)(smf + 128 + fh*32 + 8*nc + 2*t);
                hbA[nc*4+0] = fmaxf(hbA[nc*4+0] + bb.x, 0.f);
                hbA[nc*4+1] = fmaxf(hbA[nc*4+1] + bb.y, 0.f);
                hbA[nc*4+2] = fmaxf(hbA[nc*4+2] + bb.x, 0.f);
                hbA[nc*4+3] = fmaxf(hbA[nc*4+3] + bb.y, 0.f);
                hbB[nc*4+0] = fmaxf(hbB[nc*4+0] + bb.x, 0.f);
                hbB[nc*4+1] = fmaxf(hbB[nc*4+1] + bb.y, 0.f);
                hbB[nc*4+2] = fmaxf(hbB[nc*4+2] + bb.x, 0.f);
                hbB[nc*4+3] = fmaxf(hbB[nc*4+3] + bb.y, 0.f);
            }
            uint32_t hahA[8], hahB[8];
            c2a_hi<2>(hbA, hahA);
            c2a_hi<2>(hbB, hahB);
            gemm1w<2,4,72>(zvA, zvB, hahA, hahB, sm16 + W2H + fh*32, g, t);
        }

        // ---- z = y + (accumulated) + b2; store ----
        float2 *opA = (float2*)(out + b0 * 512);
#pragma unroll
        for (int nc = 0; nc < 4; nc++) {
            float2 bb = *(const float2*)(smf + 192 + 8*nc + 2*t);
            opA[g*16 + nc*4 + t]     = make_float2(zvA[nc*4+0] + yvA[nc*4+0] + bb.x,
                                                   zvA[nc*4+1] + yvA[nc*4+1] + bb.y);
            opA[(g+8)*16 + nc*4 + t] = make_float2(zvA[nc*4+2] + yvA[nc*4+2] + bb.x,
                                                   zvA[nc*4+3] + yvA[nc*4+3] + bb.y);
        }
        if (v1) {
            float2 *opB = (float2*)(out + b1s * 512);
#pragma unroll
            for (int nc = 0; nc < 4; nc++) {
                float2 bb = *(const float2*)(smf + 192 + 8*nc + 2*t);
                opB[g*16 + nc*4 + t]     = make_float2(zvB[nc*4+0] + yvB[nc*4+0] + bb.x,
                                                       zvB[nc*4+1] + yvB[nc*4+1] + bb.y);
                opB[(g+8)*16 + nc*4 + t] = make_float2(zvB[nc*4+2] + yvB[nc*4+2] + bb.x,
                                                       zvB[nc*4+3] + yvB[nc*4+3] + bb.y);
            }
        }
        __syncwarp();   // staging reuse barrier for next pair
    }
}

extern "C" void kernel_launch(void* const* d_in, const int* in_sizes, int n_in,
                              void* d_out, int out_size)
{
    const float* x  = (const float*)d_in[0];
    const float* Wq = (const float*)d_in[1];
    const float* bq = (const float*)d_in[2];
    const float* Wk = (const float*)d_in[3];
    const float* bk = (const float*)d_in[4];
    const float* Wv = (const float*)d_in[5];
    const float* bv = (const float*)d_in[6];
    const float* Wo = (const float*)d_in[7];
    const float* bo = (const float*)d_in[8];
    const float* W1 = (const float*)d_in[9];
    const float* b1 = (const float*)d_in[10];
    const float* W2 = (const float*)d_in[11];
    const float* b2 = (const float*)d_in[12];
    float* out = (float*)d_out;

    const int B = in_sizes[0] / 512;                                    // 65536
    const int blocks = (B + BATCHES_PER_BLOCK - 1) / BATCHES_PER_BLOCK; // 2048

    cudaFuncSetAttribute(tinyformer_tc_kernel,
                         cudaFuncAttributeMaxDynamicSharedMemorySize, SMEM_BYTES);
    tinyformer_tc_kernel<<<blocks, THREADS, SMEM_BYTES>>>(x, Wq, bq, Wk, bk, Wv, bv,
                                                          Wo, bo, W1, b1, W2, b2, out, B);
}